// round 6
// baseline (speedup 1.0000x reference)
#include <cuda_runtime.h>
#include <math.h>
#include <stdint.h>

// Dims
constexpr int DS  = 256;   // S
constexpr int DN  = 768;   // N
constexpr int DCM = 64;    // CM
constexpr int DCZ = 128;   // CZ
constexpr int DH  = 8;     // heads
constexpr int DCH = 32;    // per-head channels
constexpr int DHC = 256;   // H*CH
constexpr int DSN = DS * DN;          // 196608 rows of m
constexpr int DNN = DN * DN;          // 589824 pairs
constexpr int DCOL = DS * DCH;        // 8192 GEMM cols

// Scratch (device globals; no allocations allowed)
__device__ float d_v[DH * DN * DS * DCH];   // [h][j][s][d]
__device__ float d_g[DSN * DHC];            // [s*N+j][hc]
__device__ float d_b[DH * DN * DN];         // [h][i][j]  (logits -> softmax in place)
__device__ float d_o[DH * DN * DS * DCH];   // [h][i][s][d]

__device__ __forceinline__ float to_tf32(float x) {
    uint32_t u;
    asm("cvt.rna.tf32.f32 %0, %1;" : "=r"(u) : "f"(x));
    return __uint_as_float(u);
}

#define MMA_TF32(acc, af, bf)                                                 \
    asm volatile(                                                             \
        "mma.sync.aligned.m16n8k8.row.col.f32.tf32.tf32.f32 "                 \
        "{%0,%1,%2,%3}, {%4,%5,%6,%7}, {%8,%9}, {%0,%1,%2,%3};"               \
        : "+f"((acc)[0]), "+f"((acc)[1]), "+f"((acc)[2]), "+f"((acc)[3])      \
        : "r"((af)[0]), "r"((af)[1]), "r"((af)[2]), "r"((af)[3]),             \
          "r"((bf)[0]), "r"((bf)[1]))

// ---------------------------------------------------------------------------
// K1 (tensor): LN(m) then [128 x 64] @ [64 x 128] per block via tf32 mma.
// grid = (1536, 4); blockIdx.y picks 128 of the 512 fused output cols
// (cols 0-255 = v via Wm, 256-511 = g via Wg).
// ---------------------------------------------------------------------------
constexpr int K1A = 68;
constexpr int K1B = 136;
constexpr int K1_SMEM = (128 * K1A + 64 * K1B + 64 + 64) * 4;

__global__ void k1_ln_vg_tc(const float* __restrict__ m,
                            const float* __restrict__ nw,
                            const float* __restrict__ nb,
                            const float* __restrict__ Wm,
                            const float* __restrict__ Wg) {
    extern __shared__ float sm1[];
    float* As  = sm1;                    // [128][68]
    float* Bs  = As + 128 * K1A;         // [64][136]
    float* snw = Bs + 64 * K1B;          // [64]
    float* snb = snw + 64;               // [64]

    const int tid = threadIdx.x;
    const int gr0 = blockIdx.x * 128;
    const int bn0 = blockIdx.y * 128;    // global output col base

    #pragma unroll
    for (int t = 0; t < 8; t++) {
        int f = tid + t * 256;
        int r = f >> 4;
        int k = (f & 15) << 2;
        float4 v4 = *(const float4*)&m[(size_t)(gr0 + r) * DCM + k];
        *(float4*)&As[r * K1A + k] = v4;
    }
    const float* Wsrc = (bn0 < 256) ? (Wm + (size_t)bn0 * DCM)
                                    : (Wg + (size_t)(bn0 - 256) * DCM);
    #pragma unroll
    for (int t = 0; t < 32; t++) {
        int idx = tid + t * 256;
        int n = idx >> 6;
        int k = idx & 63;
        Bs[k * K1B + n] = to_tf32(Wsrc[n * DCM + k]);
    }
    if (tid < 64) { snw[tid] = nw[tid]; snb[tid] = nb[tid]; }
    __syncthreads();

    if (tid < 128) {
        float s1 = 0.f, s2 = 0.f;
        #pragma unroll
        for (int k = 0; k < 64; k++) {
            float x = As[tid * K1A + k];
            s1 += x; s2 += x * x;
        }
        float mu  = s1 * (1.f / 64.f);
        float var = s2 * (1.f / 64.f) - mu * mu;
        float inv = rsqrtf(var + 1e-5f);
        #pragma unroll
        for (int k = 0; k < 64; k++) {
            float x = As[tid * K1A + k];
            As[tid * K1A + k] = to_tf32((x - mu) * inv * snw[k] + snb[k]);
        }
    }
    __syncthreads();

    const int lane = tid & 31;
    const int wid  = tid >> 5;
    const int warp_m = wid >> 2;
    const int warp_n = wid & 3;
    const int gid = lane >> 2;
    const int tq  = lane & 3;

    float acc[4][4][4];
    #pragma unroll
    for (int i = 0; i < 4; i++)
        #pragma unroll
        for (int j = 0; j < 4; j++)
            #pragma unroll
            for (int r = 0; r < 4; r++) acc[i][j][r] = 0.f;

    #pragma unroll
    for (int k8 = 0; k8 < 8; k8++) {
        uint32_t af[4][4], bf[4][2];
        #pragma unroll
        for (int mt = 0; mt < 4; mt++) {
            int row = warp_m * 64 + mt * 16 + gid;
            af[mt][0] = __float_as_uint(As[row * K1A + k8 * 8 + tq]);
            af[mt][1] = __float_as_uint(As[(row + 8) * K1A + k8 * 8 + tq]);
            af[mt][2] = __float_as_uint(As[row * K1A + k8 * 8 + tq + 4]);
            af[mt][3] = __float_as_uint(As[(row + 8) * K1A + k8 * 8 + tq + 4]);
        }
        #pragma unroll
        for (int nt = 0; nt < 4; nt++) {
            int col = warp_n * 32 + nt * 8 + gid;
            bf[nt][0] = __float_as_uint(Bs[(k8 * 8 + tq) * K1B + col]);
            bf[nt][1] = __float_as_uint(Bs[(k8 * 8 + tq + 4) * K1B + col]);
        }
        #pragma unroll
        for (int mt = 0; mt < 4; mt++)
            #pragma unroll
            for (int nt = 0; nt < 4; nt++)
                MMA_TF32(acc[mt][nt], af[mt], bf[nt]);
    }

    #pragma unroll
    for (int mt = 0; mt < 4; mt++) {
        #pragma unroll
        for (int half = 0; half < 2; half++) {
            int rowg = gr0 + warp_m * 64 + mt * 16 + gid + half * 8;
            int ss = rowg / DN;
            int jj = rowg - ss * DN;
            #pragma unroll
            for (int nt = 0; nt < 4; nt++) {
                int cglob = bn0 + warp_n * 32 + nt * 8 + tq * 2;
                float c0 = acc[mt][nt][half * 2];
                float c1 = acc[mt][nt][half * 2 + 1];
                if (cglob < 256) {
                    int h = cglob >> 5, d = cglob & 31;
                    *(float2*)&d_v[((size_t)(h * DN + jj) * DS + ss) * DCH + d] =
                        make_float2(c0, c1);
                } else {
                    int cg = cglob - 256;
                    float g0 = 1.f / (1.f + __expf(-c0));
                    float g1 = 1.f / (1.f + __expf(-c1));
                    *(float2*)&d_g[(size_t)rowg * DHC + cg] = make_float2(g0, g1);
                }
            }
        }
    }
}

// ---------------------------------------------------------------------------
// K2: LN(z) + b[h][i][j] = dot(zln, Wz[h]) + mask penalty. One warp per pair.
// ---------------------------------------------------------------------------
__global__ void k2_ln_bias(const float* __restrict__ z,
                           const int* __restrict__ mask,
                           const float* __restrict__ nw,
                           const float* __restrict__ nb,
                           const float* __restrict__ Wz) {
    int gwarp = (blockIdx.x * blockDim.x + threadIdx.x) >> 5;
    int l = threadIdx.x & 31;
    if (gwarp >= DNN) return;

    const float* zr = z + (size_t)gwarp * DCZ;
    float4 xv = *(const float4*)&zr[l * 4];
    float s1 = xv.x + xv.y + xv.z + xv.w;
    float s2 = xv.x * xv.x + xv.y * xv.y + xv.z * xv.z + xv.w * xv.w;
    #pragma unroll
    for (int off = 16; off; off >>= 1) {
        s1 += __shfl_xor_sync(0xffffffffu, s1, off);
        s2 += __shfl_xor_sync(0xffffffffu, s2, off);
    }
    float mu = s1 * (1.f / 128.f);
    float inv = rsqrtf(s2 * (1.f / 128.f) - mu * mu + 1e-5f);
    float4 wv = *(const float4*)&nw[l * 4];
    float4 bv = *(const float4*)&nb[l * 4];
    float xn0 = (xv.x - mu) * inv * wv.x + bv.x;
    float xn1 = (xv.y - mu) * inv * wv.y + bv.y;
    float xn2 = (xv.z - mu) * inv * wv.z + bv.z;
    float xn3 = (xv.w - mu) * inv * wv.w + bv.w;

    float myb = 0.f;
    #pragma unroll
    for (int h = 0; h < DH; h++) {
        float4 w4 = *(const float4*)&Wz[h * DCZ + l * 4];
        float p = xn0 * w4.x + xn1 * w4.y + xn2 * w4.z + xn3 * w4.w;
        #pragma unroll
        for (int off = 16; off; off >>= 1)
            p += __shfl_xor_sync(0xffffffffu, p, off);
        if (l == h) myb = p;
    }
    if (l < DH) {
        float pen = (mask[gwarp] != 0) ? 0.f : -1e6f;
        d_b[(size_t)l * DNN + gwarp] = myb + pen;
    }
}

// ---------------------------------------------------------------------------
// K3: softmax over j (768) per (h,i) row. In place on d_b.
// ---------------------------------------------------------------------------
__global__ void k3_softmax() {
    __shared__ float sd[256];
    float* p = d_b + (size_t)blockIdx.x * DN;
    int tid = threadIdx.x;
    float x0 = p[tid], x1 = p[tid + 256], x2 = p[tid + 512];
    float mx = fmaxf(x0, fmaxf(x1, x2));
    sd[tid] = mx; __syncthreads();
    #pragma unroll
    for (int s = 128; s; s >>= 1) {
        if (tid < s) sd[tid] = fmaxf(sd[tid], sd[tid + s]);
        __syncthreads();
    }
    float bm = sd[0]; __syncthreads();
    float e0 = __expf(x0 - bm), e1 = __expf(x1 - bm), e2 = __expf(x2 - bm);
    sd[tid] = e0 + e1 + e2; __syncthreads();
    #pragma unroll
    for (int s = 128; s; s >>= 1) {
        if (tid < s) sd[tid] += sd[tid + s];
        __syncthreads();
    }
    float invs = 1.f / sd[0];
    p[tid] = e0 * invs; p[tid + 256] = e1 * invs; p[tid + 512] = e2 * invs;
}

// ---------------------------------------------------------------------------
// K4 v2: per-head GEMM, tf32 mma.sync, 128x128 block, 8 warps (2x4),
// warp tile 64x32. Fragment-packed XOR-swizzled smem (LDS.128 fragment
// loads, conflict-free) + double-buffered stages (1 sync per k16).
//
// Packed layout: P[row][16]; element k of the k16 tile stored at float index
//   ((k & 3) ^ (row & 3)) * 4 + (k >> 2)
// so a single float4 at chunk (tq ^ (row&3)) yields k = {tq, tq+4, tq+8, tq+12}.
// ---------------------------------------------------------------------------
__global__ void __launch_bounds__(256) k4_gemm_tf32_v2() {
    __shared__ float Ap[2][128][16];
    __shared__ float Bp[2][128][16];
    const int h = blockIdx.z;
    const float* A = d_b + (size_t)h * DNN;
    const float* B = d_v + (size_t)h * DN * DCOL;
    float* C = d_o + (size_t)h * DN * DCOL;
    const int bm0 = blockIdx.y * 128;
    const int bn0 = blockIdx.x * 128;
    const int tid = threadIdx.x;
    const int lane = tid & 31;
    const int wid = tid >> 5;
    const int warp_m = wid >> 2;       // 0..1
    const int warp_n = wid & 3;        // 0..3
    const int gid = lane >> 2;         // 0..7
    const int tq  = lane & 3;          // 0..3

    // loaders
    const int ar = tid >> 2;           // A row 0..63 (and +64)
    const int aslot = tid & 3;         // k>>2 slot
    const int xa = ar & 3;
    const int br = tid >> 5;           // B k-row 0..7 (and +8)
    const int bc = (tid & 31) << 2;    // B col base
    const int xb = br & 3;
    const int sb = br >> 2;            // 0..1

    float acc[4][4][4];
    #pragma unroll
    for (int i = 0; i < 4; i++)
        #pragma unroll
        for (int j = 0; j < 4; j++)
            #pragma unroll
            for (int r = 0; r < 4; r++) acc[i][j][r] = 0.f;

    float4 pa0 = *(const float4*)&A[(size_t)(bm0 + ar) * DN + aslot * 4];
    float4 pa1 = *(const float4*)&A[(size_t)(bm0 + ar + 64) * DN + aslot * 4];
    float4 pb0 = *(const float4*)&B[(size_t)br * DCOL + bn0 + bc];
    float4 pb1 = *(const float4*)&B[(size_t)(br + 8) * DCOL + bn0 + bc];

    // stage tile 0 into buffer 0
    {
        Ap[0][ar][((0 ^ xa) << 2) + aslot] = to_tf32(pa0.x);
        Ap[0][ar][((1 ^ xa) << 2) + aslot] = to_tf32(pa0.y);
        Ap[0][ar][((2 ^ xa) << 2) + aslot] = to_tf32(pa0.z);
        Ap[0][ar][((3 ^ xa) << 2) + aslot] = to_tf32(pa0.w);
        Ap[0][ar + 64][((0 ^ xa) << 2) + aslot] = to_tf32(pa1.x);
        Ap[0][ar + 64][((1 ^ xa) << 2) + aslot] = to_tf32(pa1.y);
        Ap[0][ar + 64][((2 ^ xa) << 2) + aslot] = to_tf32(pa1.z);
        Ap[0][ar + 64][((3 ^ xa) << 2) + aslot] = to_tf32(pa1.w);
        Bp[0][bc + 0][((xb ^ 0) << 2) + sb] = to_tf32(pb0.x);
        Bp[0][bc + 1][((xb ^ 1) << 2) + sb] = to_tf32(pb0.y);
        Bp[0][bc + 2][((xb ^ 2) << 2) + sb] = to_tf32(pb0.z);
        Bp[0][bc + 3][((xb ^ 3) << 2) + sb] = to_tf32(pb0.w);
        Bp[0][bc + 0][((xb ^ 0) << 2) + sb + 2] = to_tf32(pb1.x);
        Bp[0][bc + 1][((xb ^ 1) << 2) + sb + 2] = to_tf32(pb1.y);
        Bp[0][bc + 2][((xb ^ 2) << 2) + sb + 2] = to_tf32(pb1.z);
        Bp[0][bc + 3][((xb ^ 3) << 2) + sb + 2] = to_tf32(pb1.w);
    }
    __syncthreads();

    const int csel = (tq ^ (gid & 3)) << 2;
    int cur = 0;

    for (int k0 = 0; k0 < DN; k0 += 16) {
        const int kn = k0 + 16;
        const bool more = (kn < DN);
        if (more) {
            pa0 = *(const float4*)&A[(size_t)(bm0 + ar) * DN + kn + aslot * 4];
            pa1 = *(const float4*)&A[(size_t)(bm0 + ar + 64) * DN + kn + aslot * 4];
            pb0 = *(const float4*)&B[(size_t)(kn + br) * DCOL + bn0 + bc];
            pb1 = *(const float4*)&B[(size_t)(kn + br + 8) * DCOL + bn0 + bc];
        }

        // fragment loads: 12 x LDS.128, conflict-free
        float4 fa[4], fa2[4], fb[4];
        #pragma unroll
        for (int mt = 0; mt < 4; mt++) {
            int r = warp_m * 64 + mt * 16 + gid;
            fa[mt]  = *(float4*)&Ap[cur][r][csel];
            fa2[mt] = *(float4*)&Ap[cur][r + 8][csel];
        }
        #pragma unroll
        for (int nt = 0; nt < 4; nt++) {
            int n = warp_n * 32 + nt * 8 + gid;
            fb[nt] = *(float4*)&Bp[cur][n][csel];
        }

        // k8 step 0 (k = tq, tq+4)
        #pragma unroll
        for (int mt = 0; mt < 4; mt++) {
            uint32_t af[4] = {__float_as_uint(fa[mt].x), __float_as_uint(fa2[mt].x),
                              __float_as_uint(fa[mt].y), __float_as_uint(fa2[mt].y)};
            #pragma unroll
            for (int nt = 0; nt < 4; nt++) {
                uint32_t bf[2] = {__float_as_uint(fb[nt].x), __float_as_uint(fb[nt].y)};
                MMA_TF32(acc[mt][nt], af, bf);
            }
        }
        // k8 step 1 (k = tq+8, tq+12)
        #pragma unroll
        for (int mt = 0; mt < 4; mt++) {
            uint32_t af[4] = {__float_as_uint(fa[mt].z), __float_as_uint(fa2[mt].z),
                              __float_as_uint(fa[mt].w), __float_as_uint(fa2[mt].w)};
            #pragma unroll
            for (int nt = 0; nt < 4; nt++) {
                uint32_t bf[2] = {__float_as_uint(fb[nt].z), __float_as_uint(fb[nt].w)};
                MMA_TF32(acc[mt][nt], af, bf);
            }
        }

        if (more) {
            const int nxt = cur ^ 1;
            Ap[nxt][ar][((0 ^ xa) << 2) + aslot] = to_tf32(pa0.x);
            Ap[nxt][ar][((1 ^ xa) << 2) + aslot] = to_tf32(pa0.y);
            Ap[nxt][ar][((2 ^ xa) << 2) + aslot] = to_tf32(pa0.z);
            Ap[nxt][ar][((3 ^ xa) << 2) + aslot] = to_tf32(pa0.w);
            Ap[nxt][ar + 64][((0 ^ xa) << 2) + aslot] = to_tf32(pa1.x);
            Ap[nxt][ar + 64][((1 ^ xa) << 2) + aslot] = to_tf32(pa1.y);
            Ap[nxt][ar + 64][((2 ^ xa) << 2) + aslot] = to_tf32(pa1.z);
            Ap[nxt][ar + 64][((3 ^ xa) << 2) + aslot] = to_tf32(pa1.w);
            Bp[nxt][bc + 0][((xb ^ 0) << 2) + sb] = to_tf32(pb0.x);
            Bp[nxt][bc + 1][((xb ^ 1) << 2) + sb] = to_tf32(pb0.y);
            Bp[nxt][bc + 2][((xb ^ 2) << 2) + sb] = to_tf32(pb0.z);
            Bp[nxt][bc + 3][((xb ^ 3) << 2) + sb] = to_tf32(pb0.w);
            Bp[nxt][bc + 0][((xb ^ 0) << 2) + sb + 2] = to_tf32(pb1.x);
            Bp[nxt][bc + 1][((xb ^ 1) << 2) + sb + 2] = to_tf32(pb1.y);
            Bp[nxt][bc + 2][((xb ^ 2) << 2) + sb + 2] = to_tf32(pb1.z);
            Bp[nxt][bc + 3][((xb ^ 3) << 2) + sb + 2] = to_tf32(pb1.w);
        }
        __syncthreads();
        cur ^= 1;
    }

    #pragma unroll
    for (int mt = 0; mt < 4; mt++) {
        #pragma unroll
        for (int nt = 0; nt < 4; nt++) {
            int row = bm0 + warp_m * 64 + mt * 16 + gid;
            int col = bn0 + warp_n * 32 + nt * 8 + tq * 2;
            *(float2*)&C[(size_t)row * DCOL + col] =
                make_float2(acc[mt][nt][0], acc[mt][nt][1]);
            *(float2*)&C[(size_t)(row + 8) * DCOL + col] =
                make_float2(acc[mt][nt][2], acc[mt][nt][3]);
        }
    }
}

// ---------------------------------------------------------------------------
// K5 (tensor): out[128 x 64] += (g*o_gather)[128 x 256] @ WoT[256 x 64]
// ---------------------------------------------------------------------------
constexpr int K5A = 68;
constexpr int K5B = 72;
constexpr int K5_SMEM = (128 * K5A + 64 * K5B) * 4;

__global__ void k5_out_tc(const float* __restrict__ Wo, float* __restrict__ out) {
    extern __shared__ float sm5[];
    float* As = sm5;                 // [128][68]
    float* Bs = As + 128 * K5A;      // [64][72]

    const int tid = threadIdx.x;
    const int gr0 = blockIdx.x * 128;
    const int ss = gr0 / DN;
    const int i0 = gr0 - ss * DN;

    const int lane = tid & 31;
    const int wid  = tid >> 5;
    const int warp_m = wid >> 1;
    const int warp_n = wid & 1;
    const int gid = lane >> 2;
    const int tq  = lane & 3;

    float acc[2][4][4];
    #pragma unroll
    for (int i = 0; i < 2; i++)
        #pragma unroll
        for (int j = 0; j < 4; j++)
            #pragma unroll
            for (int r = 0; r < 4; r++) acc[i][j][r] = 0.f;

    for (int ck0 = 0; ck0 < DHC; ck0 += 64) {
        #pragma unroll
        for (int t = 0; t < 16; t++) {
            int idx = tid + t * 256;
            int n = idx >> 6, cl = idx & 63;
            Bs[cl * K5B + n] = to_tf32(Wo[n * DHC + ck0 + cl]);
        }
        #pragma unroll
        for (int t = 0; t < 32; t++) {
            int idx = tid + t * 256;
            int r = idx >> 6, cl = idx & 63;
            int c = ck0 + cl;
            int h = c >> 5, d = c & 31;
            float ov = d_o[((size_t)(h * DN + i0 + r) * DS + ss) * DCH + d];
            float gv = d_g[(size_t)(gr0 + r) * DHC + c];
            As[r * K5A + cl] = to_tf32(gv * ov);
        }
        __syncthreads();

        #pragma unroll
        for (int k8 = 0; k8 < 8; k8++) {
            uint32_t af[2][4], bf[4][2];
            #pragma unroll
            for (int mt = 0; mt < 2; mt++) {
                int row = warp_m * 32 + mt * 16 + gid;
                af[mt][0] = __float_as_uint(As[row * K5A + k8 * 8 + tq]);
                af[mt][1] = __float_as_uint(As[(row + 8) * K5A + k8 * 8 + tq]);
                af[mt][2] = __float_as_uint(As[row * K5A + k8 * 8 + tq + 4]);
                af[mt][3] = __float_as_uint(As[(row + 8) * K5A + k8 * 8 + tq + 4]);
            }
            #pragma unroll
            for (int nt = 0; nt < 4; nt++) {
                int col = warp_n * 32 + nt * 8 + gid;
                bf[nt][0] = __float_as_uint(Bs[(k8 * 8 + tq) * K5B + col]);
                bf[nt][1] = __float_as_uint(Bs[(k8 * 8 + tq + 4) * K5B + col]);
            }
            #pragma unroll
            for (int mt = 0; mt < 2; mt++)
                #pragma unroll
                for (int nt = 0; nt < 4; nt++)
                    MMA_TF32(acc[mt][nt], af[mt], bf[nt]);
        }
        __syncthreads();
    }

    #pragma unroll
    for (int mt = 0; mt < 2; mt++) {
        #pragma unroll
        for (int nt = 0; nt < 4; nt++) {
            int row = gr0 + warp_m * 32 + mt * 16 + gid;
            int col = warp_n * 32 + nt * 8 + tq * 2;
            *(float2*)&out[(size_t)row * DCM + col] =
                make_float2(acc[mt][nt][0], acc[mt][nt][1]);
            *(float2*)&out[(size_t)(row + 8) * DCM + col] =
                make_float2(acc[mt][nt][2], acc[mt][nt][3]);
        }
    }
}

// ---------------------------------------------------------------------------
extern "C" void kernel_launch(void* const* d_in, const int* in_sizes, int n_in,
                              void* d_out, int out_size) {
    const float* m    = (const float*)d_in[0];
    const float* z    = (const float*)d_in[1];
    const int*   mask = (const int*)d_in[2];
    const float* nmw  = (const float*)d_in[3];
    const float* nmb  = (const float*)d_in[4];
    const float* nzw  = (const float*)d_in[5];
    const float* nzb  = (const float*)d_in[6];
    const float* Wm   = (const float*)d_in[7];
    const float* Wg   = (const float*)d_in[8];
    const float* Wz   = (const float*)d_in[9];
    const float* Wo   = (const float*)d_in[10];
    float* out = (float*)d_out;

    cudaFuncSetAttribute(k1_ln_vg_tc, cudaFuncAttributeMaxDynamicSharedMemorySize, K1_SMEM);
    cudaFuncSetAttribute(k5_out_tc,   cudaFuncAttributeMaxDynamicSharedMemorySize, K5_SMEM);

    dim3 g1(DSN / 128, 4);
    k1_ln_vg_tc<<<g1, 256, K1_SMEM>>>(m, nmw, nmb, Wm, Wg);
    k2_ln_bias<<<DNN / 8, 256>>>(z, mask, nzw, nzb, Wz);
    k3_softmax<<<DH * DN, 256>>>();
    dim3 g4(DCOL / 128, DN / 128, DH);
    k4_gemm_tf32_v2<<<g4, 256>>>();
    k5_out_tc<<<DSN / 128, 256, K5_SMEM>>>(Wo, out);
}

// round 7
// speedup vs baseline: 2.4736x; 2.4736x over previous
#include <cuda_runtime.h>
#include <cuda_fp16.h>
#include <math.h>
#include <stdint.h>

// Dims
constexpr int DS  = 256;   // S
constexpr int DN  = 768;   // N
constexpr int DCM = 64;    // CM
constexpr int DCZ = 128;   // CZ
constexpr int DH  = 8;     // heads
constexpr int DCH = 32;    // per-head channels
constexpr int DHC = 256;   // H*CH
constexpr int DSN = DS * DN;          // 196608 rows of m
constexpr int DNN = DN * DN;          // 589824 pairs
constexpr int DCOL = DS * DCH;        // 8192 GEMM cols

// Scratch (device globals; no allocations allowed)
__device__ __half d_vt[(size_t)DH * DCOL * DN];  // v^T fp16: [h][n=s*32+d][j]
__device__ __half d_bh[(size_t)DH * DNN];        // softmax probs fp16: [h][i][j]
__device__ float  d_g[(size_t)DSN * DHC];        // [s*N+j][hc]
__device__ float  d_b[(size_t)DH * DNN];         // logits f32 (K2 -> K3)
__device__ float  d_o[(size_t)DH * DN * DCOL];   // [h][i][s*32+d]

__device__ __forceinline__ float to_tf32(float x) {
    uint32_t u;
    asm("cvt.rna.tf32.f32 %0, %1;" : "=r"(u) : "f"(x));
    return __uint_as_float(u);
}

#define MMA_TF32(acc, af, bf)                                                 \
    asm volatile(                                                             \
        "mma.sync.aligned.m16n8k8.row.col.f32.tf32.tf32.f32 "                 \
        "{%0,%1,%2,%3}, {%4,%5,%6,%7}, {%8,%9}, {%0,%1,%2,%3};"               \
        : "+f"((acc)[0]), "+f"((acc)[1]), "+f"((acc)[2]), "+f"((acc)[3])      \
        : "r"((af)[0]), "r"((af)[1]), "r"((af)[2]), "r"((af)[3]),             \
          "r"((bf)[0]), "r"((bf)[1]))

#define MMA_F16(acc, af, bf)                                                  \
    asm volatile(                                                             \
        "mma.sync.aligned.m16n8k16.row.col.f32.f16.f16.f32 "                  \
        "{%0,%1,%2,%3}, {%4,%5,%6,%7}, {%8,%9}, {%0,%1,%2,%3};"               \
        : "+f"((acc)[0]), "+f"((acc)[1]), "+f"((acc)[2]), "+f"((acc)[3])      \
        : "r"((af)[0]), "r"((af)[1]), "r"((af)[2]), "r"((af)[3]),             \
          "r"((bf)[0]), "r"((bf)[1]))

// ---------------------------------------------------------------------------
// K1 (tensor, tf32): LN(m) then
//   y in {0,1}: v^T = Wm_tile @ mln^T  -> d_vt[h][n][j] (fp16, operands swapped)
//   y in {2,3}: g = sigmoid(mln @ Wg^T) -> d_g (f32)
// ---------------------------------------------------------------------------
constexpr int K1A = 68;
constexpr int K1B = 136;
constexpr int K1_SMEM = (128 * K1A + 128 * K1A + 64 + 64) * 4;

__global__ void k1_ln_vg_tc(const float* __restrict__ m,
                            const float* __restrict__ nw,
                            const float* __restrict__ nb,
                            const float* __restrict__ Wm,
                            const float* __restrict__ Wg) {
    extern __shared__ float sm1[];
    float* As  = sm1;                    // [128][68] mln (tf32)
    float* Ws  = sm1 + 128 * K1A;        // v-path: [128 col][68]; g-path: Bs[64][136]
    float* snw = Ws + 128 * K1A;
    float* snb = snw + 64;

    const int tid = threadIdx.x;
    const int gr0 = blockIdx.x * 128;
    const int bn0 = blockIdx.y * 128;
    const bool vpath = (bn0 < 256);

    #pragma unroll
    for (int t = 0; t < 8; t++) {
        int f = tid + t * 256;
        int r = f >> 4;
        int k = (f & 15) << 2;
        float4 v4 = *(const float4*)&m[(size_t)(gr0 + r) * DCM + k];
        *(float4*)&As[r * K1A + k] = v4;
    }
    if (vpath) {
        #pragma unroll
        for (int t = 0; t < 32; t++) {
            int idx = tid + t * 256;
            int c = idx >> 6, k = idx & 63;
            Ws[c * K1A + k] = to_tf32(Wm[(size_t)(bn0 + c) * DCM + k]);
        }
    } else {
        #pragma unroll
        for (int t = 0; t < 32; t++) {
            int idx = tid + t * 256;
            int n = idx >> 6, k = idx & 63;
            Ws[k * K1B + n] = to_tf32(Wg[(size_t)(bn0 - 256 + n) * DCM + k]);
        }
    }
    if (tid < 64) { snw[tid] = nw[tid]; snb[tid] = nb[tid]; }
    __syncthreads();

    if (tid < 128) {
        float s1 = 0.f, s2 = 0.f;
        #pragma unroll
        for (int k = 0; k < 64; k++) {
            float x = As[tid * K1A + k];
            s1 += x; s2 += x * x;
        }
        float mu  = s1 * (1.f / 64.f);
        float var = s2 * (1.f / 64.f) - mu * mu;
        float inv = rsqrtf(var + 1e-5f);
        #pragma unroll
        for (int k = 0; k < 64; k++) {
            float x = As[tid * K1A + k];
            As[tid * K1A + k] = to_tf32((x - mu) * inv * snw[k] + snb[k]);
        }
    }
    __syncthreads();

    const int lane = tid & 31;
    const int wid  = tid >> 5;
    const int warp_m = wid >> 2;
    const int warp_n = wid & 3;
    const int gid = lane >> 2;
    const int tq  = lane & 3;

    float acc[4][4][4];
    #pragma unroll
    for (int i = 0; i < 4; i++)
        #pragma unroll
        for (int j = 0; j < 4; j++)
            #pragma unroll
            for (int r = 0; r < 4; r++) acc[i][j][r] = 0.f;

    if (vpath) {
        // A = Ws (v-cols x k), B = As (m-rows as n)
        #pragma unroll
        for (int k8 = 0; k8 < 8; k8++) {
            uint32_t af[4][4], bf[4][2];
            #pragma unroll
            for (int mt = 0; mt < 4; mt++) {
                int c = warp_m * 64 + mt * 16 + gid;
                af[mt][0] = __float_as_uint(Ws[c * K1A + k8 * 8 + tq]);
                af[mt][1] = __float_as_uint(Ws[(c + 8) * K1A + k8 * 8 + tq]);
                af[mt][2] = __float_as_uint(Ws[c * K1A + k8 * 8 + tq + 4]);
                af[mt][3] = __float_as_uint(Ws[(c + 8) * K1A + k8 * 8 + tq + 4]);
            }
            #pragma unroll
            for (int nt = 0; nt < 4; nt++) {
                int rl = warp_n * 32 + nt * 8 + gid;
                bf[nt][0] = __float_as_uint(As[rl * K1A + k8 * 8 + tq]);
                bf[nt][1] = __float_as_uint(As[rl * K1A + k8 * 8 + tq + 4]);
            }
            #pragma unroll
            for (int mt = 0; mt < 4; mt++)
                #pragma unroll
                for (int nt = 0; nt < 4; nt++)
                    MMA_TF32(acc[mt][nt], af[mt], bf[nt]);
        }
        const int ss = gr0 / DN;
        const int jj0 = gr0 - ss * DN;   // 768 % 128 == 0: no straddle
        #pragma unroll
        for (int mt = 0; mt < 4; mt++) {
            #pragma unroll
            for (int half = 0; half < 2; half++) {
                int col = bn0 + warp_m * 64 + mt * 16 + gid + half * 8;
                int hh = col >> 5, dd = col & 31;
                __half* dst = d_vt + ((size_t)hh * DCOL + ss * DCH + dd) * DN + jj0;
                #pragma unroll
                for (int nt = 0; nt < 4; nt++) {
                    int jloc = warp_n * 32 + nt * 8 + tq * 2;
                    *(__half2*)&dst[jloc] =
                        __floats2half2_rn(acc[mt][nt][half * 2],
                                          acc[mt][nt][half * 2 + 1]);
                }
            }
        }
    } else {
        #pragma unroll
        for (int k8 = 0; k8 < 8; k8++) {
            uint32_t af[4][4], bf[4][2];
            #pragma unroll
            for (int mt = 0; mt < 4; mt++) {
                int row = warp_m * 64 + mt * 16 + gid;
                af[mt][0] = __float_as_uint(As[row * K1A + k8 * 8 + tq]);
                af[mt][1] = __float_as_uint(As[(row + 8) * K1A + k8 * 8 + tq]);
                af[mt][2] = __float_as_uint(As[row * K1A + k8 * 8 + tq + 4]);
                af[mt][3] = __float_as_uint(As[(row + 8) * K1A + k8 * 8 + tq + 4]);
            }
            #pragma unroll
            for (int nt = 0; nt < 4; nt++) {
                int col = warp_n * 32 + nt * 8 + gid;
                bf[nt][0] = __float_as_uint(Ws[(k8 * 8 + tq) * K1B + col]);
                bf[nt][1] = __float_as_uint(Ws[(k8 * 8 + tq + 4) * K1B + col]);
            }
            #pragma unroll
            for (int mt = 0; mt < 4; mt++)
                #pragma unroll
                for (int nt = 0; nt < 4; nt++)
                    MMA_TF32(acc[mt][nt], af[mt], bf[nt]);
        }
        #pragma unroll
        for (int mt = 0; mt < 4; mt++) {
            #pragma unroll
            for (int half = 0; half < 2; half++) {
                int rowg = gr0 + warp_m * 64 + mt * 16 + gid + half * 8;
                #pragma unroll
                for (int nt = 0; nt < 4; nt++) {
                    int cg = (bn0 - 256) + warp_n * 32 + nt * 8 + tq * 2;
                    float g0 = 1.f / (1.f + __expf(-acc[mt][nt][half * 2]));
                    float g1 = 1.f / (1.f + __expf(-acc[mt][nt][half * 2 + 1]));
                    *(float2*)&d_g[(size_t)rowg * DHC + cg] = make_float2(g0, g1);
                }
            }
        }
    }
}

// ---------------------------------------------------------------------------
// K2: LN(z) + b[h][i][j] = dot(zln, Wz[h]) + mask penalty. One warp per pair.
// ---------------------------------------------------------------------------
__global__ void k2_ln_bias(const float* __restrict__ z,
                           const int* __restrict__ mask,
                           const float* __restrict__ nw,
                           const float* __restrict__ nb,
                           const float* __restrict__ Wz) {
    int gwarp = (blockIdx.x * blockDim.x + threadIdx.x) >> 5;
    int l = threadIdx.x & 31;
    if (gwarp >= DNN) return;

    const float* zr = z + (size_t)gwarp * DCZ;
    float4 xv = *(const float4*)&zr[l * 4];
    float s1 = xv.x + xv.y + xv.z + xv.w;
    float s2 = xv.x * xv.x + xv.y * xv.y + xv.z * xv.z + xv.w * xv.w;
    #pragma unroll
    for (int off = 16; off; off >>= 1) {
        s1 += __shfl_xor_sync(0xffffffffu, s1, off);
        s2 += __shfl_xor_sync(0xffffffffu, s2, off);
    }
    float mu = s1 * (1.f / 128.f);
    float inv = rsqrtf(s2 * (1.f / 128.f) - mu * mu + 1e-5f);
    float4 wv = *(const float4*)&nw[l * 4];
    float4 bv = *(const float4*)&nb[l * 4];
    float xn0 = (xv.x - mu) * inv * wv.x + bv.x;
    float xn1 = (xv.y - mu) * inv * wv.y + bv.y;
    float xn2 = (xv.z - mu) * inv * wv.z + bv.z;
    float xn3 = (xv.w - mu) * inv * wv.w + bv.w;

    float myb = 0.f;
    #pragma unroll
    for (int h = 0; h < DH; h++) {
        float4 w4 = *(const float4*)&Wz[h * DCZ + l * 4];
        float p = xn0 * w4.x + xn1 * w4.y + xn2 * w4.z + xn3 * w4.w;
        #pragma unroll
        for (int off = 16; off; off >>= 1)
            p += __shfl_xor_sync(0xffffffffu, p, off);
        if (l == h) myb = p;
    }
    if (l < DH) {
        float pen = (mask[gwarp] != 0) ? 0.f : -1e6f;
        d_b[(size_t)l * DNN + gwarp] = myb + pen;
    }
}

// ---------------------------------------------------------------------------
// K3: softmax over j (768) per (h,i) row. Reads d_b f32, writes d_bh fp16.
// ---------------------------------------------------------------------------
__global__ void k3_softmax() {
    __shared__ float sd[256];
    const float* p = d_b + (size_t)blockIdx.x * DN;
    __half* q = d_bh + (size_t)blockIdx.x * DN;
    int tid = threadIdx.x;
    float x0 = p[tid], x1 = p[tid + 256], x2 = p[tid + 512];
    float mx = fmaxf(x0, fmaxf(x1, x2));
    sd[tid] = mx; __syncthreads();
    #pragma unroll
    for (int s = 128; s; s >>= 1) {
        if (tid < s) sd[tid] = fmaxf(sd[tid], sd[tid + s]);
        __syncthreads();
    }
    float bm = sd[0]; __syncthreads();
    float e0 = __expf(x0 - bm), e1 = __expf(x1 - bm), e2 = __expf(x2 - bm);
    sd[tid] = e0 + e1 + e2; __syncthreads();
    #pragma unroll
    for (int s = 128; s; s >>= 1) {
        if (tid < s) sd[tid] += sd[tid + s];
        __syncthreads();
    }
    float invs = 1.f / sd[0];
    q[tid]       = __float2half_rn(e0 * invs);
    q[tid + 256] = __float2half_rn(e1 * invs);
    q[tid + 512] = __float2half_rn(e2 * invs);
}

// ---------------------------------------------------------------------------
// K4 (fp16 mma m16n8k16): C[h](768 x 8192) = P[h](768 x 768) @ V^T[h](8192 x 768)^T
// Both operands k-contiguous fp16 -> staging is a pure uint4 copy.
// Block 128x128, 8 warps (2x4), warp tile 64x32, k16 per iter (48 iters).
// smem rows padded to 24 halfs (stride 12 words) -> conflict-free LDS.32.
// ---------------------------------------------------------------------------
__global__ void __launch_bounds__(256) k4_gemm_fp16() {
    __shared__ __half As[128 * 24];   // [m][k16]
    __shared__ __half Bs[128 * 24];   // [n][k16]
    const int h = blockIdx.z;
    const __half* A = d_bh + (size_t)h * DNN;
    const __half* B = d_vt + (size_t)h * DCOL * DN;
    float* C = d_o + (size_t)h * DN * DCOL;
    const int bm0 = blockIdx.y * 128;
    const int bn0 = blockIdx.x * 128;
    const int tid = threadIdx.x;
    const int lane = tid & 31;
    const int wid = tid >> 5;
    const int warp_m = wid >> 2;       // 0..1
    const int warp_n = wid & 3;        // 0..3
    const int gid = lane >> 2;         // 0..7
    const int tq  = lane & 3;          // 0..3

    const int r = tid >> 1;            // 0..127
    const int sel = tid & 1;           // 0..1 (8-half halves of the k16 row)

    float acc[4][4][4];
    #pragma unroll
    for (int i = 0; i < 4; i++)
        #pragma unroll
        for (int j = 0; j < 4; j++)
            #pragma unroll
            for (int rr = 0; rr < 4; rr++) acc[i][j][rr] = 0.f;

    uint4 pa = *(const uint4*)&A[(size_t)(bm0 + r) * DN + sel * 8];
    uint4 pb = *(const uint4*)&B[(size_t)(bn0 + r) * DN + sel * 8];

    for (int k0 = 0; k0 < DN; k0 += 16) {
        *(uint4*)&As[r * 24 + sel * 8] = pa;
        *(uint4*)&Bs[r * 24 + sel * 8] = pb;
        __syncthreads();

        int kn = k0 + 16;
        if (kn < DN) {
            pa = *(const uint4*)&A[(size_t)(bm0 + r) * DN + kn + sel * 8];
            pb = *(const uint4*)&B[(size_t)(bn0 + r) * DN + kn + sel * 8];
        }

        uint32_t af[4][4], bf[4][2];
        #pragma unroll
        for (int mt = 0; mt < 4; mt++) {
            int row = warp_m * 64 + mt * 16 + gid;
            af[mt][0] = *(const uint32_t*)&As[row * 24 + tq * 2];
            af[mt][1] = *(const uint32_t*)&As[(row + 8) * 24 + tq * 2];
            af[mt][2] = *(const uint32_t*)&As[row * 24 + tq * 2 + 8];
            af[mt][3] = *(const uint32_t*)&As[(row + 8) * 24 + tq * 2 + 8];
        }
        #pragma unroll
        for (int nt = 0; nt < 4; nt++) {
            int col = warp_n * 32 + nt * 8 + gid;
            bf[nt][0] = *(const uint32_t*)&Bs[col * 24 + tq * 2];
            bf[nt][1] = *(const uint32_t*)&Bs[col * 24 + tq * 2 + 8];
        }
        #pragma unroll
        for (int mt = 0; mt < 4; mt++)
            #pragma unroll
            for (int nt = 0; nt < 4; nt++)
                MMA_F16(acc[mt][nt], af[mt], bf[nt]);
        __syncthreads();
    }

    #pragma unroll
    for (int mt = 0; mt < 4; mt++) {
        #pragma unroll
        for (int nt = 0; nt < 4; nt++) {
            int row = bm0 + warp_m * 64 + mt * 16 + gid;
            int col = bn0 + warp_n * 32 + nt * 8 + tq * 2;
            *(float2*)&C[(size_t)row * DCOL + col] =
                make_float2(acc[mt][nt][0], acc[mt][nt][1]);
            *(float2*)&C[(size_t)(row + 8) * DCOL + col] =
                make_float2(acc[mt][nt][2], acc[mt][nt][3]);
        }
    }
}

// ---------------------------------------------------------------------------
// K5 (tensor, tf32): out[128 x 64] += (g*o_gather)[128 x 256] @ WoT[256 x 64]
// ---------------------------------------------------------------------------
constexpr int K5A = 68;
constexpr int K5B = 72;
constexpr int K5_SMEM = (128 * K5A + 64 * K5B) * 4;

__global__ void k5_out_tc(const float* __restrict__ Wo, float* __restrict__ out) {
    extern __shared__ float sm5[];
    float* As = sm5;                 // [128][68]
    float* Bs = As + 128 * K5A;      // [64][72]

    const int tid = threadIdx.x;
    const int gr0 = blockIdx.x * 128;
    const int ss = gr0 / DN;
    const int i0 = gr0 - ss * DN;

    const int lane = tid & 31;
    const int wid  = tid >> 5;
    const int warp_m = wid >> 1;
    const int warp_n = wid & 1;
    const int gid = lane >> 2;
    const int tq  = lane & 3;

    float acc[2][4][4];
    #pragma unroll
    for (int i = 0; i < 2; i++)
        #pragma unroll
        for (int j = 0; j < 4; j++)
            #pragma unroll
            for (int r = 0; r < 4; r++) acc[i][j][r] = 0.f;

    for (int ck0 = 0; ck0 < DHC; ck0 += 64) {
        #pragma unroll
        for (int t = 0; t < 16; t++) {
            int idx = tid + t * 256;
            int n = idx >> 6, cl = idx & 63;
            Bs[cl * K5B + n] = to_tf32(Wo[n * DHC + ck0 + cl]);
        }
        #pragma unroll
        for (int t = 0; t < 32; t++) {
            int idx = tid + t * 256;
            int r = idx >> 6, cl = idx & 63;
            int c = ck0 + cl;
            int h = c >> 5, d = c & 31;
            float ov = d_o[((size_t)(h * DN + i0 + r) * DS + ss) * DCH + d];
            float gv = d_g[(size_t)(gr0 + r) * DHC + c];
            As[r * K5A + cl] = to_tf32(gv * ov);
        }
        __syncthreads();

        #pragma unroll
        for (int k8 = 0; k8 < 8; k8++) {
            uint32_t af[2][4], bf[4][2];
            #pragma unroll
            for (int mt = 0; mt < 2; mt++) {
                int row = warp_m * 32 + mt * 16 + gid;
                af[mt][0] = __float_as_uint(As[row * K5A + k8 * 8 + tq]);
                af[mt][1] = __float_as_uint(As[(row + 8) * K5A + k8 * 8 + tq]);
                af[mt][2] = __float_as_uint(As[row * K5A + k8 * 8 + tq + 4]);
                af[mt][3] = __float_as_uint(As[(row + 8) * K5A + k8 * 8 + tq + 4]);
            }
            #pragma unroll
            for (int nt = 0; nt < 4; nt++) {
                int col = warp_n * 32 + nt * 8 + gid;
                bf[nt][0] = __float_as_uint(Bs[(k8 * 8 + tq) * K5B + col]);
                bf[nt][1] = __float_as_uint(Bs[(k8 * 8 + tq + 4) * K5B + col]);
            }
            #pragma unroll
            for (int mt = 0; mt < 2; mt++)
                #pragma unroll
                for (int nt = 0; nt < 4; nt++)
                    MMA_TF32(acc[mt][nt], af[mt], bf[nt]);
        }
        __syncthreads();
    }

    #pragma unroll
    for (int mt = 0; mt < 2; mt++) {
        #pragma unroll
        for (int nt = 0; nt < 4; nt++) {
            int row = gr0 + warp_m * 32 + mt * 16 + gid;
            int col = warp_n * 32 + nt * 8 + tq * 2;
            *(float2*)&out[(size_t)row * DCM + col] =
                make_float2(acc[mt][nt][0], acc[mt][nt][1]);
            *(float2*)&out[(size_t)(row + 8) * DCM + col] =
                make_float2(acc[mt][nt][2], acc[mt][nt][3]);
        }
    }
}

// ---------------------------------------------------------------------------
extern "C" void kernel_launch(void* const* d_in, const int* in_sizes, int n_in,
                              void* d_out, int out_size) {
    const float* m    = (const float*)d_in[0];
    const float* z    = (const float*)d_in[1];
    const int*   mask = (const int*)d_in[2];
    const float* nmw  = (const float*)d_in[3];
    const float* nmb  = (const float*)d_in[4];
    const float* nzw  = (const float*)d_in[5];
    const float* nzb  = (const float*)d_in[6];
    const float* Wm   = (const float*)d_in[7];
    const float* Wg   = (const float*)d_in[8];
    const float* Wz   = (const float*)d_in[9];
    const float* Wo   = (const float*)d_in[10];
    float* out = (float*)d_out;

    cudaFuncSetAttribute(k1_ln_vg_tc, cudaFuncAttributeMaxDynamicSharedMemorySize, K1_SMEM);
    cudaFuncSetAttribute(k5_out_tc,   cudaFuncAttributeMaxDynamicSharedMemorySize, K5_SMEM);

    dim3 g1(DSN / 128, 4);
    k1_ln_vg_tc<<<g1, 256, K1_SMEM>>>(m, nmw, nmb, Wm, Wg);
    k2_ln_bias<<<DNN / 8, 256>>>(z, mask, nzw, nzb, Wz);
    k3_softmax<<<DH * DN, 256>>>();
    dim3 g4(DCOL / 128, DN / 128, DH);
    k4_gemm_fp16<<<g4, 256>>>();
    k5_out_tc<<<DSN / 128, 256, K5_SMEM>>>(Wo, out);
}

// round 8
// speedup vs baseline: 2.4843x; 1.0043x over previous
#include <cuda_runtime.h>
#include <cuda_fp16.h>
#include <math.h>
#include <stdint.h>

// Dims
constexpr int DS  = 256;   // S
constexpr int DN  = 768;   // N
constexpr int DCM = 64;    // CM
constexpr int DCZ = 128;   // CZ
constexpr int DH  = 8;     // heads
constexpr int DCH = 32;    // per-head channels
constexpr int DHC = 256;   // H*CH
constexpr int DSN = DS * DN;          // 196608 rows of m
constexpr int DNN = DN * DN;          // 589824 pairs
constexpr int DCOL = DS * DCH;        // 8192 GEMM cols

// Scratch (device globals; no allocations allowed)
__device__ __half d_vt[(size_t)DH * DCOL * DN];  // v^T fp16: [h][n=s*32+d][j]
__device__ __half d_bh[(size_t)DH * DNN];        // softmax probs fp16: [h][i][j]
__device__ __half d_gh[(size_t)DSN * DHC];       // gate fp16: [s*N+j][hc]
__device__ float  d_b[(size_t)DH * DNN];         // logits f32 (K2 -> K3)
__device__ __half d_oh[(size_t)DH * DN * DCOL];  // o fp16: [h][i][s*32+d]

__device__ __forceinline__ float to_tf32(float x) {
    uint32_t u;
    asm("cvt.rna.tf32.f32 %0, %1;" : "=r"(u) : "f"(x));
    return __uint_as_float(u);
}

#define MMA_TF32(acc, af, bf)                                                 \
    asm volatile(                                                             \
        "mma.sync.aligned.m16n8k8.row.col.f32.tf32.tf32.f32 "                 \
        "{%0,%1,%2,%3}, {%4,%5,%6,%7}, {%8,%9}, {%0,%1,%2,%3};"               \
        : "+f"((acc)[0]), "+f"((acc)[1]), "+f"((acc)[2]), "+f"((acc)[3])      \
        : "r"((af)[0]), "r"((af)[1]), "r"((af)[2]), "r"((af)[3]),             \
          "r"((bf)[0]), "r"((bf)[1]))

#define MMA_F16(acc, af, bf)                                                  \
    asm volatile(                                                             \
        "mma.sync.aligned.m16n8k16.row.col.f32.f16.f16.f32 "                  \
        "{%0,%1,%2,%3}, {%4,%5,%6,%7}, {%8,%9}, {%0,%1,%2,%3};"               \
        : "+f"((acc)[0]), "+f"((acc)[1]), "+f"((acc)[2]), "+f"((acc)[3])      \
        : "r"((af)[0]), "r"((af)[1]), "r"((af)[2]), "r"((af)[3]),             \
          "r"((bf)[0]), "r"((bf)[1]))

// ---------------------------------------------------------------------------
// K1 (tensor, tf32): LN(m) then
//   y in {0,1}: v^T = Wm_tile @ mln^T  -> d_vt[h][n][j] (fp16, operands swapped)
//   y in {2,3}: g = sigmoid(mln @ Wg^T) -> d_gh (fp16)
// ---------------------------------------------------------------------------
constexpr int K1A = 68;
constexpr int K1B = 136;
constexpr int K1_SMEM = (128 * K1A + 128 * K1A + 64 + 64) * 4;

__global__ void k1_ln_vg_tc(const float* __restrict__ m,
                            const float* __restrict__ nw,
                            const float* __restrict__ nb,
                            const float* __restrict__ Wm,
                            const float* __restrict__ Wg) {
    extern __shared__ float sm1[];
    float* As  = sm1;                    // [128][68] mln (tf32)
    float* Ws  = sm1 + 128 * K1A;        // v-path: [128 col][68]; g-path: Bs[64][136]
    float* snw = Ws + 128 * K1A;
    float* snb = snw + 64;

    const int tid = threadIdx.x;
    const int gr0 = blockIdx.x * 128;
    const int bn0 = blockIdx.y * 128;
    const bool vpath = (bn0 < 256);

    #pragma unroll
    for (int t = 0; t < 8; t++) {
        int f = tid + t * 256;
        int r = f >> 4;
        int k = (f & 15) << 2;
        float4 v4 = *(const float4*)&m[(size_t)(gr0 + r) * DCM + k];
        *(float4*)&As[r * K1A + k] = v4;
    }
    if (vpath) {
        #pragma unroll
        for (int t = 0; t < 32; t++) {
            int idx = tid + t * 256;
            int c = idx >> 6, k = idx & 63;
            Ws[c * K1A + k] = to_tf32(Wm[(size_t)(bn0 + c) * DCM + k]);
        }
    } else {
        #pragma unroll
        for (int t = 0; t < 32; t++) {
            int idx = tid + t * 256;
            int n = idx >> 6, k = idx & 63;
            Ws[k * K1B + n] = to_tf32(Wg[(size_t)(bn0 - 256 + n) * DCM + k]);
        }
    }
    if (tid < 64) { snw[tid] = nw[tid]; snb[tid] = nb[tid]; }
    __syncthreads();

    if (tid < 128) {
        float s1 = 0.f, s2 = 0.f;
        #pragma unroll
        for (int k = 0; k < 64; k++) {
            float x = As[tid * K1A + k];
            s1 += x; s2 += x * x;
        }
        float mu  = s1 * (1.f / 64.f);
        float var = s2 * (1.f / 64.f) - mu * mu;
        float inv = rsqrtf(var + 1e-5f);
        #pragma unroll
        for (int k = 0; k < 64; k++) {
            float x = As[tid * K1A + k];
            As[tid * K1A + k] = to_tf32((x - mu) * inv * snw[k] + snb[k]);
        }
    }
    __syncthreads();

    const int lane = tid & 31;
    const int wid  = tid >> 5;
    const int warp_m = wid >> 2;
    const int warp_n = wid & 3;
    const int gid = lane >> 2;
    const int tq  = lane & 3;

    float acc[4][4][4];
    #pragma unroll
    for (int i = 0; i < 4; i++)
        #pragma unroll
        for (int j = 0; j < 4; j++)
            #pragma unroll
            for (int r = 0; r < 4; r++) acc[i][j][r] = 0.f;

    if (vpath) {
        #pragma unroll
        for (int k8 = 0; k8 < 8; k8++) {
            uint32_t af[4][4], bf[4][2];
            #pragma unroll
            for (int mt = 0; mt < 4; mt++) {
                int c = warp_m * 64 + mt * 16 + gid;
                af[mt][0] = __float_as_uint(Ws[c * K1A + k8 * 8 + tq]);
                af[mt][1] = __float_as_uint(Ws[(c + 8) * K1A + k8 * 8 + tq]);
                af[mt][2] = __float_as_uint(Ws[c * K1A + k8 * 8 + tq + 4]);
                af[mt][3] = __float_as_uint(Ws[(c + 8) * K1A + k8 * 8 + tq + 4]);
            }
            #pragma unroll
            for (int nt = 0; nt < 4; nt++) {
                int rl = warp_n * 32 + nt * 8 + gid;
                bf[nt][0] = __float_as_uint(As[rl * K1A + k8 * 8 + tq]);
                bf[nt][1] = __float_as_uint(As[rl * K1A + k8 * 8 + tq + 4]);
            }
            #pragma unroll
            for (int mt = 0; mt < 4; mt++)
                #pragma unroll
                for (int nt = 0; nt < 4; nt++)
                    MMA_TF32(acc[mt][nt], af[mt], bf[nt]);
        }
        const int ss = gr0 / DN;
        const int jj0 = gr0 - ss * DN;
        #pragma unroll
        for (int mt = 0; mt < 4; mt++) {
            #pragma unroll
            for (int half = 0; half < 2; half++) {
                int col = bn0 + warp_m * 64 + mt * 16 + gid + half * 8;
                int hh = col >> 5, dd = col & 31;
                __half* dst = d_vt + ((size_t)hh * DCOL + ss * DCH + dd) * DN + jj0;
                #pragma unroll
                for (int nt = 0; nt < 4; nt++) {
                    int jloc = warp_n * 32 + nt * 8 + tq * 2;
                    *(__half2*)&dst[jloc] =
                        __floats2half2_rn(acc[mt][nt][half * 2],
                                          acc[mt][nt][half * 2 + 1]);
                }
            }
        }
    } else {
        #pragma unroll
        for (int k8 = 0; k8 < 8; k8++) {
            uint32_t af[4][4], bf[4][2];
            #pragma unroll
            for (int mt = 0; mt < 4; mt++) {
                int row = warp_m * 64 + mt * 16 + gid;
                af[mt][0] = __float_as_uint(As[row * K1A + k8 * 8 + tq]);
                af[mt][1] = __float_as_uint(As[(row + 8) * K1A + k8 * 8 + tq]);
                af[mt][2] = __float_as_uint(As[row * K1A + k8 * 8 + tq + 4]);
                af[mt][3] = __float_as_uint(As[(row + 8) * K1A + k8 * 8 + tq + 4]);
            }
            #pragma unroll
            for (int nt = 0; nt < 4; nt++) {
                int col = warp_n * 32 + nt * 8 + gid;
                bf[nt][0] = __float_as_uint(Ws[(k8 * 8 + tq) * K1B + col]);
                bf[nt][1] = __float_as_uint(Ws[(k8 * 8 + tq + 4) * K1B + col]);
            }
            #pragma unroll
            for (int mt = 0; mt < 4; mt++)
                #pragma unroll
                for (int nt = 0; nt < 4; nt++)
                    MMA_TF32(acc[mt][nt], af[mt], bf[nt]);
        }
        #pragma unroll
        for (int mt = 0; mt < 4; mt++) {
            #pragma unroll
            for (int half = 0; half < 2; half++) {
                int rowg = gr0 + warp_m * 64 + mt * 16 + gid + half * 8;
                #pragma unroll
                for (int nt = 0; nt < 4; nt++) {
                    int cg = (bn0 - 256) + warp_n * 32 + nt * 8 + tq * 2;
                    float g0 = 1.f / (1.f + __expf(-acc[mt][nt][half * 2]));
                    float g1 = 1.f / (1.f + __expf(-acc[mt][nt][half * 2 + 1]));
                    *(__half2*)&d_gh[(size_t)rowg * DHC + cg] =
                        __floats2half2_rn(g0, g1);
                }
            }
        }
    }
}

// ---------------------------------------------------------------------------
// K2: LN(z) + b[h][i][j] = dot(zln, Wz[h]) + mask penalty. One warp per pair.
// ---------------------------------------------------------------------------
__global__ void k2_ln_bias(const float* __restrict__ z,
                           const int* __restrict__ mask,
                           const float* __restrict__ nw,
                           const float* __restrict__ nb,
                           const float* __restrict__ Wz) {
    int gwarp = (blockIdx.x * blockDim.x + threadIdx.x) >> 5;
    int l = threadIdx.x & 31;
    if (gwarp >= DNN) return;

    const float* zr = z + (size_t)gwarp * DCZ;
    float4 xv = *(const float4*)&zr[l * 4];
    float s1 = xv.x + xv.y + xv.z + xv.w;
    float s2 = xv.x * xv.x + xv.y * xv.y + xv.z * xv.z + xv.w * xv.w;
    #pragma unroll
    for (int off = 16; off; off >>= 1) {
        s1 += __shfl_xor_sync(0xffffffffu, s1, off);
        s2 += __shfl_xor_sync(0xffffffffu, s2, off);
    }
    float mu = s1 * (1.f / 128.f);
    float inv = rsqrtf(s2 * (1.f / 128.f) - mu * mu + 1e-5f);
    float4 wv = *(const float4*)&nw[l * 4];
    float4 bv = *(const float4*)&nb[l * 4];
    float xn0 = (xv.x - mu) * inv * wv.x + bv.x;
    float xn1 = (xv.y - mu) * inv * wv.y + bv.y;
    float xn2 = (xv.z - mu) * inv * wv.z + bv.z;
    float xn3 = (xv.w - mu) * inv * wv.w + bv.w;

    float myb = 0.f;
    #pragma unroll
    for (int h = 0; h < DH; h++) {
        float4 w4 = *(const float4*)&Wz[h * DCZ + l * 4];
        float p = xn0 * w4.x + xn1 * w4.y + xn2 * w4.z + xn3 * w4.w;
        #pragma unroll
        for (int off = 16; off; off >>= 1)
            p += __shfl_xor_sync(0xffffffffu, p, off);
        if (l == h) myb = p;
    }
    if (l < DH) {
        float pen = (mask[gwarp] != 0) ? 0.f : -1e6f;
        d_b[(size_t)l * DNN + gwarp] = myb + pen;
    }
}

// ---------------------------------------------------------------------------
// K3: softmax over j (768) per (h,i) row. Reads d_b f32, writes d_bh fp16.
// ---------------------------------------------------------------------------
__global__ void k3_softmax() {
    __shared__ float sd[256];
    const float* p = d_b + (size_t)blockIdx.x * DN;
    __half* q = d_bh + (size_t)blockIdx.x * DN;
    int tid = threadIdx.x;
    float x0 = p[tid], x1 = p[tid + 256], x2 = p[tid + 512];
    float mx = fmaxf(x0, fmaxf(x1, x2));
    sd[tid] = mx; __syncthreads();
    #pragma unroll
    for (int s = 128; s; s >>= 1) {
        if (tid < s) sd[tid] = fmaxf(sd[tid], sd[tid + s]);
        __syncthreads();
    }
    float bm = sd[0]; __syncthreads();
    float e0 = __expf(x0 - bm), e1 = __expf(x1 - bm), e2 = __expf(x2 - bm);
    sd[tid] = e0 + e1 + e2; __syncthreads();
    #pragma unroll
    for (int s = 128; s; s >>= 1) {
        if (tid < s) sd[tid] += sd[tid + s];
        __syncthreads();
    }
    float invs = 1.f / sd[0];
    q[tid]       = __float2half_rn(e0 * invs);
    q[tid + 256] = __float2half_rn(e1 * invs);
    q[tid + 512] = __float2half_rn(e2 * invs);
}

// ---------------------------------------------------------------------------
// K4 (fp16 mma m16n8k16): C[h](768 x 8192) = P @ V^T, output fp16 to d_oh.
// Block 128x128, 8 warps (2x4), warp tile 64x32, k16/iter. Stride 24 halfs.
// ---------------------------------------------------------------------------
__global__ void __launch_bounds__(256) k4_gemm_fp16() {
    __shared__ __half As[128 * 24];   // [m][k16]
    __shared__ __half Bs[128 * 24];   // [n][k16]
    const int h = blockIdx.z;
    const __half* A = d_bh + (size_t)h * DNN;
    const __half* B = d_vt + (size_t)h * DCOL * DN;
    __half* C = d_oh + (size_t)h * DN * DCOL;
    const int bm0 = blockIdx.y * 128;
    const int bn0 = blockIdx.x * 128;
    const int tid = threadIdx.x;
    const int lane = tid & 31;
    const int wid = tid >> 5;
    const int warp_m = wid >> 2;
    const int warp_n = wid & 3;
    const int gid = lane >> 2;
    const int tq  = lane & 3;

    const int r = tid >> 1;
    const int sel = tid & 1;

    float acc[4][4][4];
    #pragma unroll
    for (int i = 0; i < 4; i++)
        #pragma unroll
        for (int j = 0; j < 4; j++)
            #pragma unroll
            for (int rr = 0; rr < 4; rr++) acc[i][j][rr] = 0.f;

    uint4 pa = *(const uint4*)&A[(size_t)(bm0 + r) * DN + sel * 8];
    uint4 pb = *(const uint4*)&B[(size_t)(bn0 + r) * DN + sel * 8];

    for (int k0 = 0; k0 < DN; k0 += 16) {
        *(uint4*)&As[r * 24 + sel * 8] = pa;
        *(uint4*)&Bs[r * 24 + sel * 8] = pb;
        __syncthreads();

        int kn = k0 + 16;
        if (kn < DN) {
            pa = *(const uint4*)&A[(size_t)(bm0 + r) * DN + kn + sel * 8];
            pb = *(const uint4*)&B[(size_t)(bn0 + r) * DN + kn + sel * 8];
        }

        uint32_t af[4][4], bf[4][2];
        #pragma unroll
        for (int mt = 0; mt < 4; mt++) {
            int row = warp_m * 64 + mt * 16 + gid;
            af[mt][0] = *(const uint32_t*)&As[row * 24 + tq * 2];
            af[mt][1] = *(const uint32_t*)&As[(row + 8) * 24 + tq * 2];
            af[mt][2] = *(const uint32_t*)&As[row * 24 + tq * 2 + 8];
            af[mt][3] = *(const uint32_t*)&As[(row + 8) * 24 + tq * 2 + 8];
        }
        #pragma unroll
        for (int nt = 0; nt < 4; nt++) {
            int col = warp_n * 32 + nt * 8 + gid;
            bf[nt][0] = *(const uint32_t*)&Bs[col * 24 + tq * 2];
            bf[nt][1] = *(const uint32_t*)&Bs[col * 24 + tq * 2 + 8];
        }
        #pragma unroll
        for (int mt = 0; mt < 4; mt++)
            #pragma unroll
            for (int nt = 0; nt < 4; nt++)
                MMA_F16(acc[mt][nt], af[mt], bf[nt]);
        __syncthreads();
    }

    #pragma unroll
    for (int mt = 0; mt < 4; mt++) {
        #pragma unroll
        for (int nt = 0; nt < 4; nt++) {
            int row = bm0 + warp_m * 64 + mt * 16 + gid;
            int col = bn0 + warp_n * 32 + nt * 8 + tq * 2;
            *(__half2*)&C[(size_t)row * DCOL + col] =
                __floats2half2_rn(acc[mt][nt][0], acc[mt][nt][1]);
            *(__half2*)&C[(size_t)(row + 8) * DCOL + col] =
                __floats2half2_rn(acc[mt][nt][2], acc[mt][nt][3]);
        }
    }
}

// ---------------------------------------------------------------------------
// K5 (fp16 mma): out[128 x 64] = (g*o_gather)[128 x 256] @ WoT[256 x 64]
// K chunks of 64; half2-vectorized gather+gate. Strides: 72 halfs (both tiles).
// ---------------------------------------------------------------------------
constexpr int K5ST = 72;  // halfs
constexpr int K5_SMEM = (128 * K5ST + 64 * K5ST) * 2;

__global__ void k5_out_fp16(const float* __restrict__ Wo, float* __restrict__ out) {
    extern __shared__ __half sm5h[];
    __half* As = sm5h;                  // [128][64] stride 72
    __half* Bs = As + 128 * K5ST;       // [64][64]  stride 72

    const int tid = threadIdx.x;
    const int gr0 = blockIdx.x * 128;
    const int ss = gr0 / DN;
    const int i0 = gr0 - ss * DN;

    const int lane = tid & 31;
    const int wid  = tid >> 5;
    const int warp_m = wid >> 1;        // 0..3 -> 32 rows
    const int warp_n = wid & 1;         // 0..1 -> 32 cols
    const int gid = lane >> 2;
    const int tq  = lane & 3;

    float acc[2][4][4];
    #pragma unroll
    for (int i = 0; i < 2; i++)
        #pragma unroll
        for (int j = 0; j < 4; j++)
            #pragma unroll
            for (int r = 0; r < 4; r++) acc[i][j][r] = 0.f;

    for (int ck0 = 0; ck0 < DHC; ck0 += 64) {
        // Bs[n][cl] = fp16(Wo[n][ck0+cl])
        #pragma unroll
        for (int t = 0; t < 16; t++) {
            int idx = tid + t * 256;     // 0..4095
            int n = idx >> 6, cl = idx & 63;
            Bs[n * K5ST + cl] = __float2half_rn(Wo[n * DHC + ck0 + cl]);
        }
        // As[r][cl] = fp16(g * o), half2 at a time
        #pragma unroll
        for (int t = 0; t < 16; t++) {
            int idx = tid + t * 256;     // 0..4095
            int r = idx >> 5;
            int cl = (idx & 31) * 2;
            int c = ck0 + cl;
            int h = c >> 5, d = c & 31;
            __half2 ov = *(const __half2*)&d_oh[((size_t)(h * DN + i0 + r) * DS + ss) * DCH + d];
            __half2 gv = *(const __half2*)&d_gh[(size_t)(gr0 + r) * DHC + c];
            float2 of = __half22float2(ov);
            float2 gf = __half22float2(gv);
            *(__half2*)&As[r * K5ST + cl] =
                __floats2half2_rn(gf.x * of.x, gf.y * of.y);
        }
        __syncthreads();

        #pragma unroll
        for (int k16 = 0; k16 < 4; k16++) {
            uint32_t af[2][4], bf[4][2];
            #pragma unroll
            for (int mt = 0; mt < 2; mt++) {
                int row = warp_m * 32 + mt * 16 + gid;
                af[mt][0] = *(const uint32_t*)&As[row * K5ST + k16 * 16 + tq * 2];
                af[mt][1] = *(const uint32_t*)&As[(row + 8) * K5ST + k16 * 16 + tq * 2];
                af[mt][2] = *(const uint32_t*)&As[row * K5ST + k16 * 16 + tq * 2 + 8];
                af[mt][3] = *(const uint32_t*)&As[(row + 8) * K5ST + k16 * 16 + tq * 2 + 8];
            }
            #pragma unroll
            for (int nt = 0; nt < 4; nt++) {
                int col = warp_n * 32 + nt * 8 + gid;
                bf[nt][0] = *(const uint32_t*)&Bs[col * K5ST + k16 * 16 + tq * 2];
                bf[nt][1] = *(const uint32_t*)&Bs[col * K5ST + k16 * 16 + tq * 2 + 8];
            }
            #pragma unroll
            for (int mt = 0; mt < 2; mt++)
                #pragma unroll
                for (int nt = 0; nt < 4; nt++)
                    MMA_F16(acc[mt][nt], af[mt], bf[nt]);
        }
        __syncthreads();
    }

    #pragma unroll
    for (int mt = 0; mt < 2; mt++) {
        #pragma unroll
        for (int nt = 0; nt < 4; nt++) {
            int row = gr0 + warp_m * 32 + mt * 16 + gid;
            int col = warp_n * 32 + nt * 8 + tq * 2;
            *(float2*)&out[(size_t)row * DCM + col] =
                make_float2(acc[mt][nt][0], acc[mt][nt][1]);
            *(float2*)&out[(size_t)(row + 8) * DCM + col] =
                make_float2(acc[mt][nt][2], acc[mt][nt][3]);
        }
    }
}

// ---------------------------------------------------------------------------
extern "C" void kernel_launch(void* const* d_in, const int* in_sizes, int n_in,
                              void* d_out, int out_size) {
    const float* m    = (const float*)d_in[0];
    const float* z    = (const float*)d_in[1];
    const int*   mask = (const int*)d_in[2];
    const float* nmw  = (const float*)d_in[3];
    const float* nmb  = (const float*)d_in[4];
    const float* nzw  = (const float*)d_in[5];
    const float* nzb  = (const float*)d_in[6];
    const float* Wm   = (const float*)d_in[7];
    const float* Wg   = (const float*)d_in[8];
    const float* Wz   = (const float*)d_in[9];
    const float* Wo   = (const float*)d_in[10];
    float* out = (float*)d_out;

    cudaFuncSetAttribute(k1_ln_vg_tc, cudaFuncAttributeMaxDynamicSharedMemorySize, K1_SMEM);
    cudaFuncSetAttribute(k5_out_fp16, cudaFuncAttributeMaxDynamicSharedMemorySize, K5_SMEM);

    dim3 g1(DSN / 128, 4);
    k1_ln_vg_tc<<<g1, 256, K1_SMEM>>>(m, nmw, nmb, Wm, Wg);
    k2_ln_bias<<<DNN / 8, 256>>>(z, mask, nzw, nzb, Wz);
    k3_softmax<<<DH * DN, 256>>>();
    dim3 g4(DCOL / 128, DN / 128, DH);
    k4_gemm_fp16<<<g4, 256>>>();
    k5_out_fp16<<<DSN / 128, 256, K5_SMEM>>>(Wo, out);
}

// round 9
// speedup vs baseline: 2.5528x; 1.0276x over previous
#include <cuda_runtime.h>
#include <cuda_fp16.h>
#include <math.h>
#include <stdint.h>

// Dims
constexpr int DS  = 256;   // S
constexpr int DN  = 768;   // N
constexpr int DCM = 64;    // CM
constexpr int DCZ = 128;   // CZ
constexpr int DH  = 8;     // heads
constexpr int DCH = 32;    // per-head channels
constexpr int DHC = 256;   // H*CH
constexpr int DSN = DS * DN;          // 196608 rows of m
constexpr int DNN = DN * DN;          // 589824 pairs
constexpr int DCOL = DS * DCH;        // 8192 GEMM cols

// Scratch (device globals; no allocations allowed)
__device__ __half d_vt[(size_t)DH * DCOL * DN];  // v^T fp16: [h][n=s*32+d][j]
__device__ __half d_bh[(size_t)DH * DNN];        // softmax probs fp16: [h][i][j]
__device__ __half d_gh[(size_t)DSN * DHC];       // gate fp16: [s*N+j][hc]
__device__ float  d_b[(size_t)DH * DNN];         // logits f32 (K2 -> K3)
__device__ __half d_oh[(size_t)DH * DN * DCOL];  // o fp16: [h][i][s*32+d]

__device__ __forceinline__ float to_tf32(float x) {
    uint32_t u;
    asm("cvt.rna.tf32.f32 %0, %1;" : "=r"(u) : "f"(x));
    return __uint_as_float(u);
}

__device__ __forceinline__ uint32_t smem_u32(const void* p) {
    uint32_t a;
    asm("{ .reg .u64 t; cvta.to.shared.u64 t, %1; cvt.u32.u64 %0, t; }"
        : "=r"(a) : "l"(p));
    return a;
}

#define MMA_TF32(acc, af, bf)                                                 \
    asm volatile(                                                             \
        "mma.sync.aligned.m16n8k8.row.col.f32.tf32.tf32.f32 "                 \
        "{%0,%1,%2,%3}, {%4,%5,%6,%7}, {%8,%9}, {%0,%1,%2,%3};"               \
        : "+f"((acc)[0]), "+f"((acc)[1]), "+f"((acc)[2]), "+f"((acc)[3])      \
        : "r"((af)[0]), "r"((af)[1]), "r"((af)[2]), "r"((af)[3]),             \
          "r"((bf)[0]), "r"((bf)[1]))

#define MMA_F16(acc, af, bf)                                                  \
    asm volatile(                                                             \
        "mma.sync.aligned.m16n8k16.row.col.f32.f16.f16.f32 "                  \
        "{%0,%1,%2,%3}, {%4,%5,%6,%7}, {%8,%9}, {%0,%1,%2,%3};"               \
        : "+f"((acc)[0]), "+f"((acc)[1]), "+f"((acc)[2]), "+f"((acc)[3])      \
        : "r"((af)[0]), "r"((af)[1]), "r"((af)[2]), "r"((af)[3]),             \
          "r"((bf)[0]), "r"((bf)[1]))

#define LDSM_X4(r0, r1, r2, r3, addr)                                         \
    asm volatile("ldmatrix.sync.aligned.m8n8.x4.shared.b16 {%0,%1,%2,%3}, [%4];" \
        : "=r"(r0), "=r"(r1), "=r"(r2), "=r"(r3) : "r"(addr))

// ---------------------------------------------------------------------------
// K1 (tensor, tf32): LN(m) then
//   y in {0,1}: v^T = Wm_tile @ mln^T  -> d_vt[h][n][j] (fp16, operands swapped)
//   y in {2,3}: g = sigmoid(mln @ Wg^T) -> d_gh (fp16)
// ---------------------------------------------------------------------------
constexpr int K1A = 68;
constexpr int K1B = 136;
constexpr int K1_SMEM = (128 * K1A + 128 * K1A + 64 + 64) * 4;

__global__ void k1_ln_vg_tc(const float* __restrict__ m,
                            const float* __restrict__ nw,
                            const float* __restrict__ nb,
                            const float* __restrict__ Wm,
                            const float* __restrict__ Wg) {
    extern __shared__ float sm1[];
    float* As  = sm1;                    // [128][68] mln (tf32)
    float* Ws  = sm1 + 128 * K1A;        // v-path: [128 col][68]; g-path: Bs[64][136]
    float* snw = Ws + 128 * K1A;
    float* snb = snw + 64;

    const int tid = threadIdx.x;
    const int gr0 = blockIdx.x * 128;
    const int bn0 = blockIdx.y * 128;
    const bool vpath = (bn0 < 256);

    #pragma unroll
    for (int t = 0; t < 8; t++) {
        int f = tid + t * 256;
        int r = f >> 4;
        int k = (f & 15) << 2;
        float4 v4 = *(const float4*)&m[(size_t)(gr0 + r) * DCM + k];
        *(float4*)&As[r * K1A + k] = v4;
    }
    if (vpath) {
        #pragma unroll
        for (int t = 0; t < 32; t++) {
            int idx = tid + t * 256;
            int c = idx >> 6, k = idx & 63;
            Ws[c * K1A + k] = to_tf32(Wm[(size_t)(bn0 + c) * DCM + k]);
        }
    } else {
        #pragma unroll
        for (int t = 0; t < 32; t++) {
            int idx = tid + t * 256;
            int n = idx >> 6, k = idx & 63;
            Ws[k * K1B + n] = to_tf32(Wg[(size_t)(bn0 - 256 + n) * DCM + k]);
        }
    }
    if (tid < 64) { snw[tid] = nw[tid]; snb[tid] = nb[tid]; }
    __syncthreads();

    if (tid < 128) {
        float s1 = 0.f, s2 = 0.f;
        #pragma unroll
        for (int k = 0; k < 64; k++) {
            float x = As[tid * K1A + k];
            s1 += x; s2 += x * x;
        }
        float mu  = s1 * (1.f / 64.f);
        float var = s2 * (1.f / 64.f) - mu * mu;
        float inv = rsqrtf(var + 1e-5f);
        #pragma unroll
        for (int k = 0; k < 64; k++) {
            float x = As[tid * K1A + k];
            As[tid * K1A + k] = to_tf32((x - mu) * inv * snw[k] + snb[k]);
        }
    }
    __syncthreads();

    const int lane = tid & 31;
    const int wid  = tid >> 5;
    const int warp_m = wid >> 2;
    const int warp_n = wid & 3;
    const int gid = lane >> 2;
    const int tq  = lane & 3;

    float acc[4][4][4];
    #pragma unroll
    for (int i = 0; i < 4; i++)
        #pragma unroll
        for (int j = 0; j < 4; j++)
            #pragma unroll
            for (int r = 0; r < 4; r++) acc[i][j][r] = 0.f;

    if (vpath) {
        #pragma unroll
        for (int k8 = 0; k8 < 8; k8++) {
            uint32_t af[4][4], bf[4][2];
            #pragma unroll
            for (int mt = 0; mt < 4; mt++) {
                int c = warp_m * 64 + mt * 16 + gid;
                af[mt][0] = __float_as_uint(Ws[c * K1A + k8 * 8 + tq]);
                af[mt][1] = __float_as_uint(Ws[(c + 8) * K1A + k8 * 8 + tq]);
                af[mt][2] = __float_as_uint(Ws[c * K1A + k8 * 8 + tq + 4]);
                af[mt][3] = __float_as_uint(Ws[(c + 8) * K1A + k8 * 8 + tq + 4]);
            }
            #pragma unroll
            for (int nt = 0; nt < 4; nt++) {
                int rl = warp_n * 32 + nt * 8 + gid;
                bf[nt][0] = __float_as_uint(As[rl * K1A + k8 * 8 + tq]);
                bf[nt][1] = __float_as_uint(As[rl * K1A + k8 * 8 + tq + 4]);
            }
            #pragma unroll
            for (int mt = 0; mt < 4; mt++)
                #pragma unroll
                for (int nt = 0; nt < 4; nt++)
                    MMA_TF32(acc[mt][nt], af[mt], bf[nt]);
        }
        const int ss = gr0 / DN;
        const int jj0 = gr0 - ss * DN;
        #pragma unroll
        for (int mt = 0; mt < 4; mt++) {
            #pragma unroll
            for (int half = 0; half < 2; half++) {
                int col = bn0 + warp_m * 64 + mt * 16 + gid + half * 8;
                int hh = col >> 5, dd = col & 31;
                __half* dst = d_vt + ((size_t)hh * DCOL + ss * DCH + dd) * DN + jj0;
                #pragma unroll
                for (int nt = 0; nt < 4; nt++) {
                    int jloc = warp_n * 32 + nt * 8 + tq * 2;
                    *(__half2*)&dst[jloc] =
                        __floats2half2_rn(acc[mt][nt][half * 2],
                                          acc[mt][nt][half * 2 + 1]);
                }
            }
        }
    } else {
        #pragma unroll
        for (int k8 = 0; k8 < 8; k8++) {
            uint32_t af[4][4], bf[4][2];
            #pragma unroll
            for (int mt = 0; mt < 4; mt++) {
                int row = warp_m * 64 + mt * 16 + gid;
                af[mt][0] = __float_as_uint(As[row * K1A + k8 * 8 + tq]);
                af[mt][1] = __float_as_uint(As[(row + 8) * K1A + k8 * 8 + tq]);
                af[mt][2] = __float_as_uint(As[row * K1A + k8 * 8 + tq + 4]);
                af[mt][3] = __float_as_uint(As[(row + 8) * K1A + k8 * 8 + tq + 4]);
            }
            #pragma unroll
            for (int nt = 0; nt < 4; nt++) {
                int col = warp_n * 32 + nt * 8 + gid;
                bf[nt][0] = __float_as_uint(Ws[(k8 * 8 + tq) * K1B + col]);
                bf[nt][1] = __float_as_uint(Ws[(k8 * 8 + tq + 4) * K1B + col]);
            }
            #pragma unroll
            for (int mt = 0; mt < 4; mt++)
                #pragma unroll
                for (int nt = 0; nt < 4; nt++)
                    MMA_TF32(acc[mt][nt], af[mt], bf[nt]);
        }
        #pragma unroll
        for (int mt = 0; mt < 4; mt++) {
            #pragma unroll
            for (int half = 0; half < 2; half++) {
                int rowg = gr0 + warp_m * 64 + mt * 16 + gid + half * 8;
                #pragma unroll
                for (int nt = 0; nt < 4; nt++) {
                    int cg = (bn0 - 256) + warp_n * 32 + nt * 8 + tq * 2;
                    float g0 = 1.f / (1.f + __expf(-acc[mt][nt][half * 2]));
                    float g1 = 1.f / (1.f + __expf(-acc[mt][nt][half * 2 + 1]));
                    *(__half2*)&d_gh[(size_t)rowg * DHC + cg] =
                        __floats2half2_rn(g0, g1);
                }
            }
        }
    }
}

// ---------------------------------------------------------------------------
// K2: LN(z) + b[h][i][j] = dot(zln, Wz[h]) + mask penalty. One warp per pair.
// ---------------------------------------------------------------------------
__global__ void k2_ln_bias(const float* __restrict__ z,
                           const int* __restrict__ mask,
                           const float* __restrict__ nw,
                           const float* __restrict__ nb,
                           const float* __restrict__ Wz) {
    int gwarp = (blockIdx.x * blockDim.x + threadIdx.x) >> 5;
    int l = threadIdx.x & 31;
    if (gwarp >= DNN) return;

    const float* zr = z + (size_t)gwarp * DCZ;
    float4 xv = *(const float4*)&zr[l * 4];
    float s1 = xv.x + xv.y + xv.z + xv.w;
    float s2 = xv.x * xv.x + xv.y * xv.y + xv.z * xv.z + xv.w * xv.w;
    #pragma unroll
    for (int off = 16; off; off >>= 1) {
        s1 += __shfl_xor_sync(0xffffffffu, s1, off);
        s2 += __shfl_xor_sync(0xffffffffu, s2, off);
    }
    float mu = s1 * (1.f / 128.f);
    float inv = rsqrtf(s2 * (1.f / 128.f) - mu * mu + 1e-5f);
    float4 wv = *(const float4*)&nw[l * 4];
    float4 bv = *(const float4*)&nb[l * 4];
    float xn0 = (xv.x - mu) * inv * wv.x + bv.x;
    float xn1 = (xv.y - mu) * inv * wv.y + bv.y;
    float xn2 = (xv.z - mu) * inv * wv.z + bv.z;
    float xn3 = (xv.w - mu) * inv * wv.w + bv.w;

    float myb = 0.f;
    #pragma unroll
    for (int h = 0; h < DH; h++) {
        float4 w4 = *(const float4*)&Wz[h * DCZ + l * 4];
        float p = xn0 * w4.x + xn1 * w4.y + xn2 * w4.z + xn3 * w4.w;
        #pragma unroll
        for (int off = 16; off; off >>= 1)
            p += __shfl_xor_sync(0xffffffffu, p, off);
        if (l == h) myb = p;
    }
    if (l < DH) {
        float pen = (mask[gwarp] != 0) ? 0.f : -1e6f;
        d_b[(size_t)l * DNN + gwarp] = myb + pen;
    }
}

// ---------------------------------------------------------------------------
// K3: softmax over j (768) per (h,i) row. Reads d_b f32, writes d_bh fp16.
// ---------------------------------------------------------------------------
__global__ void k3_softmax() {
    __shared__ float sd[256];
    const float* p = d_b + (size_t)blockIdx.x * DN;
    __half* q = d_bh + (size_t)blockIdx.x * DN;
    int tid = threadIdx.x;
    float x0 = p[tid], x1 = p[tid + 256], x2 = p[tid + 512];
    float mx = fmaxf(x0, fmaxf(x1, x2));
    sd[tid] = mx; __syncthreads();
    #pragma unroll
    for (int s = 128; s; s >>= 1) {
        if (tid < s) sd[tid] = fmaxf(sd[tid], sd[tid + s]);
        __syncthreads();
    }
    float bm = sd[0]; __syncthreads();
    float e0 = __expf(x0 - bm), e1 = __expf(x1 - bm), e2 = __expf(x2 - bm);
    sd[tid] = e0 + e1 + e2; __syncthreads();
    #pragma unroll
    for (int s = 128; s; s >>= 1) {
        if (tid < s) sd[tid] += sd[tid + s];
        __syncthreads();
    }
    float invs = 1.f / sd[0];
    q[tid]       = __float2half_rn(e0 * invs);
    q[tid + 256] = __float2half_rn(e1 * invs);
    q[tid + 512] = __float2half_rn(e2 * invs);
}

// ---------------------------------------------------------------------------
// K4 v3 (fp16 mma + ldmatrix + double buffer):
// C[h](768 x 8192) = P @ V^T, output fp16 to d_oh.
// Block 128x128, 8 warps (2x4), warp tile 64x32, k16/iter (48 iters).
// smem [2][128][24] halfs per operand; 48B row stride -> ldmatrix conflict-free.
// One __syncthreads per k16.
// ---------------------------------------------------------------------------
constexpr int K4ST = 24;                       // halfs per row
constexpr int K4BUF = 128 * K4ST;              // halfs per buffer

__global__ void __launch_bounds__(256) k4_gemm_fp16_v3() {
    __shared__ __half As[2][K4BUF];
    __shared__ __half Bs[2][K4BUF];
    const int h = blockIdx.z;
    const __half* A = d_bh + (size_t)h * DNN;
    const __half* B = d_vt + (size_t)h * DCOL * DN;
    __half* C = d_oh + (size_t)h * DN * DCOL;
    const int bm0 = blockIdx.y * 128;
    const int bn0 = blockIdx.x * 128;
    const int tid = threadIdx.x;
    const int lane = tid & 31;
    const int wid = tid >> 5;
    const int warp_m = wid >> 2;       // 0..1
    const int warp_n = wid & 3;        // 0..3
    const int gid = lane >> 2;
    const int tq  = lane & 3;

    const int r = tid >> 1;            // staging row 0..127
    const int sel = tid & 1;           // 8-half half of the k16 row

    // ldmatrix lane-address offsets (bytes), row stride 48B
    const uint32_t as_base = smem_u32(&As[0][0]);
    const uint32_t bs_base = smem_u32(&Bs[0][0]);
    const uint32_t a_lane = (uint32_t)((warp_m * 64 + (lane & 15)) * 48 + (lane >> 4) * 16);
    const uint32_t b_lane = (uint32_t)((warp_n * 32 + (lane & 7) + ((lane >> 4) & 1) * 8) * 48
                                       + ((lane >> 3) & 1) * 16);
    constexpr uint32_t BUFB = K4BUF * 2;   // bytes per buffer

    float acc[4][4][4];
    #pragma unroll
    for (int i = 0; i < 4; i++)
        #pragma unroll
        for (int j = 0; j < 4; j++)
            #pragma unroll
            for (int rr = 0; rr < 4; rr++) acc[i][j][rr] = 0.f;

    // stage tile 0
    {
        uint4 pa = *(const uint4*)&A[(size_t)(bm0 + r) * DN + sel * 8];
        uint4 pb = *(const uint4*)&B[(size_t)(bn0 + r) * DN + sel * 8];
        *(uint4*)&As[0][r * K4ST + sel * 8] = pa;
        *(uint4*)&Bs[0][r * K4ST + sel * 8] = pb;
    }
    __syncthreads();

    for (int c = 0; c < 48; c++) {
        const int cur = c & 1;
        const bool more = (c + 1 < 48);
        uint4 pa, pb;
        if (more) {
            int kn = (c + 1) * 16;
            pa = *(const uint4*)&A[(size_t)(bm0 + r) * DN + kn + sel * 8];
            pb = *(const uint4*)&B[(size_t)(bn0 + r) * DN + kn + sel * 8];
        }

        uint32_t af[4][4], bf[4][2];
        #pragma unroll
        for (int mt = 0; mt < 4; mt++) {
            uint32_t addr = as_base + cur * BUFB + a_lane + (uint32_t)(mt * 16 * 48);
            LDSM_X4(af[mt][0], af[mt][1], af[mt][2], af[mt][3], addr);
        }
        #pragma unroll
        for (int ntp = 0; ntp < 2; ntp++) {
            uint32_t addr = bs_base + cur * BUFB + b_lane + (uint32_t)(ntp * 16 * 48);
            LDSM_X4(bf[2 * ntp][0], bf[2 * ntp][1], bf[2 * ntp + 1][0], bf[2 * ntp + 1][1], addr);
        }
        #pragma unroll
        for (int mt = 0; mt < 4; mt++)
            #pragma unroll
            for (int nt = 0; nt < 4; nt++)
                MMA_F16(acc[mt][nt], af[mt], bf[nt]);

        if (more) {
            *(uint4*)&As[cur ^ 1][r * K4ST + sel * 8] = pa;
            *(uint4*)&Bs[cur ^ 1][r * K4ST + sel * 8] = pb;
        }
        __syncthreads();
    }

    #pragma unroll
    for (int mt = 0; mt < 4; mt++) {
        #pragma unroll
        for (int nt = 0; nt < 4; nt++) {
            int row = bm0 + warp_m * 64 + mt * 16 + gid;
            int col = bn0 + warp_n * 32 + nt * 8 + tq * 2;
            *(__half2*)&C[(size_t)row * DCOL + col] =
                __floats2half2_rn(acc[mt][nt][0], acc[mt][nt][1]);
            *(__half2*)&C[(size_t)(row + 8) * DCOL + col] =
                __floats2half2_rn(acc[mt][nt][2], acc[mt][nt][3]);
        }
    }
}

// ---------------------------------------------------------------------------
// K5 (fp16 mma): out[128 x 64] = (g*o_gather)[128 x 256] @ WoT[256 x 64]
// ---------------------------------------------------------------------------
constexpr int K5ST = 72;  // halfs
constexpr int K5_SMEM = (128 * K5ST + 64 * K5ST) * 2;

__global__ void k5_out_fp16(const float* __restrict__ Wo, float* __restrict__ out) {
    extern __shared__ __half sm5h[];
    __half* As = sm5h;                  // [128][64] stride 72
    __half* Bs = As + 128 * K5ST;       // [64][64]  stride 72

    const int tid = threadIdx.x;
    const int gr0 = blockIdx.x * 128;
    const int ss = gr0 / DN;
    const int i0 = gr0 - ss * DN;

    const int lane = tid & 31;
    const int wid  = tid >> 5;
    const int warp_m = wid >> 1;
    const int warp_n = wid & 1;
    const int gid = lane >> 2;
    const int tq  = lane & 3;

    float acc[2][4][4];
    #pragma unroll
    for (int i = 0; i < 2; i++)
        #pragma unroll
        for (int j = 0; j < 4; j++)
            #pragma unroll
            for (int r = 0; r < 4; r++) acc[i][j][r] = 0.f;

    for (int ck0 = 0; ck0 < DHC; ck0 += 64) {
        #pragma unroll
        for (int t = 0; t < 16; t++) {
            int idx = tid + t * 256;
            int n = idx >> 6, cl = idx & 63;
            Bs[n * K5ST + cl] = __float2half_rn(Wo[n * DHC + ck0 + cl]);
        }
        #pragma unroll
        for (int t = 0; t < 16; t++) {
            int idx = tid + t * 256;
            int r = idx >> 5;
            int cl = (idx & 31) * 2;
            int c = ck0 + cl;
            int h = c >> 5, d = c & 31;
            __half2 ov = *(const __half2*)&d_oh[((size_t)(h * DN + i0 + r) * DS + ss) * DCH + d];
            __half2 gv = *(const __half2*)&d_gh[(size_t)(gr0 + r) * DHC + c];
            float2 of = __half22float2(ov);
            float2 gf = __half22float2(gv);
            *(__half2*)&As[r * K5ST + cl] =
                __floats2half2_rn(gf.x * of.x, gf.y * of.y);
        }
        __syncthreads();

        #pragma unroll
        for (int k16 = 0; k16 < 4; k16++) {
            uint32_t af[2][4], bf[4][2];
            #pragma unroll
            for (int mt = 0; mt < 2; mt++) {
                int row = warp_m * 32 + mt * 16 + gid;
                af[mt][0] = *(const uint32_t*)&As[row * K5ST + k16 * 16 + tq * 2];
                af[mt][1] = *(const uint32_t*)&As[(row + 8) * K5ST + k16 * 16 + tq * 2];
                af[mt][2] = *(const uint32_t*)&As[row * K5ST + k16 * 16 + tq * 2 + 8];
                af[mt][3] = *(const uint32_t*)&As[(row + 8) * K5ST + k16 * 16 + tq * 2 + 8];
            }
            #pragma unroll
            for (int nt = 0; nt < 4; nt++) {
                int col = warp_n * 32 + nt * 8 + gid;
                bf[nt][0] = *(const uint32_t*)&Bs[col * K5ST + k16 * 16 + tq * 2];
                bf[nt][1] = *(const uint32_t*)&Bs[col * K5ST + k16 * 16 + tq * 2 + 8];
            }
            #pragma unroll
            for (int mt = 0; mt < 2; mt++)
                #pragma unroll
                for (int nt = 0; nt < 4; nt++)
                    MMA_F16(acc[mt][nt], af[mt], bf[nt]);
        }
        __syncthreads();
    }

    #pragma unroll
    for (int mt = 0; mt < 2; mt++) {
        #pragma unroll
        for (int nt = 0; nt < 4; nt++) {
            int row = gr0 + warp_m * 32 + mt * 16 + gid;
            int col = warp_n * 32 + nt * 8 + tq * 2;
            *(float2*)&out[(size_t)row * DCM + col] =
                make_float2(acc[mt][nt][0], acc[mt][nt][1]);
            *(float2*)&out[(size_t)(row + 8) * DCM + col] =
                make_float2(acc[mt][nt][2], acc[mt][nt][3]);
        }
    }
}

// ---------------------------------------------------------------------------
extern "C" void kernel_launch(void* const* d_in, const int* in_sizes, int n_in,
                              void* d_out, int out_size) {
    const float* m    = (const float*)d_in[0];
    const float* z    = (const float*)d_in[1];
    const int*   mask = (const int*)d_in[2];
    const float* nmw  = (const float*)d_in[3];
    const float* nmb  = (const float*)d_in[4];
    const float* nzw  = (const float*)d_in[5];
    const float* nzb  = (const float*)d_in[6];
    const float* Wm   = (const float*)d_in[7];
    const float* Wg   = (const float*)d_in[8];
    const float* Wz   = (const float*)d_in[9];
    const float* Wo   = (const float*)d_in[10];
    float* out = (float*)d_out;

    cudaFuncSetAttribute(k1_ln_vg_tc, cudaFuncAttributeMaxDynamicSharedMemorySize, K1_SMEM);
    cudaFuncSetAttribute(k5_out_fp16, cudaFuncAttributeMaxDynamicSharedMemorySize, K5_SMEM);

    dim3 g1(DSN / 128, 4);
    k1_ln_vg_tc<<<g1, 256, K1_SMEM>>>(m, nmw, nmb, Wm, Wg);
    k2_ln_bias<<<DNN / 8, 256>>>(z, mask, nzw, nzb, Wz);
    k3_softmax<<<DH * DN, 256>>>();
    dim3 g4(DCOL / 128, DN / 128, DH);
    k4_gemm_fp16_v3<<<g4, 256>>>();
    k5_out_fp16<<<DSN / 128, 256, K5_SMEM>>>(Wo, out);
}

// round 10
// speedup vs baseline: 2.8387x; 1.1120x over previous
#include <cuda_runtime.h>
#include <cuda_fp16.h>
#include <math.h>
#include <stdint.h>

// Dims
constexpr int DS  = 256;   // S
constexpr int DN  = 768;   // N
constexpr int DCM = 64;    // CM
constexpr int DCZ = 128;   // CZ
constexpr int DH  = 8;     // heads
constexpr int DCH = 32;    // per-head channels
constexpr int DHC = 256;   // H*CH
constexpr int DSN = DS * DN;          // 196608 rows of m
constexpr int DNN = DN * DN;          // 589824 pairs
constexpr int DCOL = DS * DCH;        // 8192 GEMM cols

// Scratch (device globals; no allocations allowed)
__device__ __half d_vt[(size_t)DH * DCOL * DN];  // v^T fp16: [h][n=s*32+d][j]
__device__ __half d_bh[(size_t)DH * DNN];        // softmax probs fp16: [h][i][j]
__device__ __half d_gh[(size_t)DSN * DHC];       // gate fp16: [s*N+j][hc]
__device__ float  d_b[(size_t)DH * DNN];         // logits f32 (K2 -> K3)
__device__ __half d_oh[(size_t)DH * DN * DCOL];  // o fp16: [h][i][s*32+d]

__device__ __forceinline__ uint32_t smem_u32(const void* p) {
    uint32_t a;
    asm("{ .reg .u64 t; cvta.to.shared.u64 t, %1; cvt.u32.u64 %0, t; }"
        : "=r"(a) : "l"(p));
    return a;
}

#define MMA_F16(acc, af, bf)                                                  \
    asm volatile(                                                             \
        "mma.sync.aligned.m16n8k16.row.col.f32.f16.f16.f32 "                  \
        "{%0,%1,%2,%3}, {%4,%5,%6,%7}, {%8,%9}, {%0,%1,%2,%3};"               \
        : "+f"((acc)[0]), "+f"((acc)[1]), "+f"((acc)[2]), "+f"((acc)[3])      \
        : "r"((af)[0]), "r"((af)[1]), "r"((af)[2]), "r"((af)[3]),             \
          "r"((bf)[0]), "r"((bf)[1]))

#define LDSM_X4(r0, r1, r2, r3, addr)                                         \
    asm volatile("ldmatrix.sync.aligned.m8n8.x4.shared.b16 {%0,%1,%2,%3}, [%4];" \
        : "=r"(r0), "=r"(r1), "=r"(r2), "=r"(r3) : "r"(addr))

// ---------------------------------------------------------------------------
// K1 v2 (fp16 mma, single pass): one CTA per 128 m-rows.
// LN once -> mh (fp16, [128][72]). Loop 4 chunks of 128 output channels:
//   chunks 0,1 (v, Wm): A = Wh (channels x k), B = mh -> coalesced d_vt writes
//   chunks 2,3 (g, Wg): A = mh, B = Wh -> sigmoid -> d_gh
// ---------------------------------------------------------------------------
constexpr int K1MH = 72;   // halfs per row (144 B stride, ldmatrix conflict-free)
constexpr int K1_SMEM = 128 * 68 * 4 + 2 * (128 * K1MH * 2) + 128 * 4;  // 72192

__global__ void __launch_bounds__(256) k1_ln_vg_v2(const float* __restrict__ m,
                                                   const float* __restrict__ nw,
                                                   const float* __restrict__ nb,
                                                   const float* __restrict__ Wm,
                                                   const float* __restrict__ Wg) {
    extern __shared__ char sm1raw[];
    float*  As  = (float*)sm1raw;                                    // [128][68]
    __half* mh  = (__half*)(sm1raw + 128 * 68 * 4);                  // [128][72]
    __half* Wh  = (__half*)(sm1raw + 128 * 68 * 4 + 128 * K1MH * 2); // [128][72]
    float*  snw = (float*)(sm1raw + 128 * 68 * 4 + 2 * 128 * K1MH * 2);
    float*  snb = snw + 64;

    const int tid = threadIdx.x;
    const int gr0 = blockIdx.x * 128;

    // load m tile [128][64]
    #pragma unroll
    for (int t = 0; t < 8; t++) {
        int f = tid + t * 256;
        int r = f >> 4;
        int k = (f & 15) << 2;
        float4 v4 = *(const float4*)&m[(size_t)(gr0 + r) * DCM + k];
        *(float4*)&As[r * 68 + k] = v4;
    }
    if (tid < 64) { snw[tid] = nw[tid]; snb[tid] = nb[tid]; }
    __syncthreads();

    // LN -> mh fp16
    if (tid < 128) {
        float s1 = 0.f, s2 = 0.f;
        #pragma unroll
        for (int k = 0; k < 64; k++) {
            float x = As[tid * 68 + k];
            s1 += x; s2 += x * x;
        }
        float mu  = s1 * (1.f / 64.f);
        float var = s2 * (1.f / 64.f) - mu * mu;
        float inv = rsqrtf(var + 1e-5f);
        #pragma unroll
        for (int k = 0; k < 64; k += 2) {
            float x0 = (As[tid * 68 + k]     - mu) * inv * snw[k]     + snb[k];
            float x1 = (As[tid * 68 + k + 1] - mu) * inv * snw[k + 1] + snb[k + 1];
            *(__half2*)&mh[tid * K1MH + k] = __floats2half2_rn(x0, x1);
        }
    }
    __syncthreads();

    const int lane = tid & 31;
    const int wid  = tid >> 5;
    const int warp_m = wid >> 2;   // 0..1
    const int warp_n = wid & 3;    // 0..3
    const int gid = lane >> 2;
    const int tq  = lane & 3;

    const uint32_t mh_base = smem_u32(mh);
    const uint32_t wh_base = smem_u32(Wh);
    const uint32_t a_lane = (uint32_t)((warp_m * 64 + (lane & 15)) * 144 + (lane >> 4) * 16);
    const uint32_t b_lane = (uint32_t)((warp_n * 32 + (lane & 7) + ((lane >> 4) & 1) * 8) * 144
                                       + ((lane >> 3) & 1) * 16);

    const int ss = gr0 / DN;
    const int jj0 = gr0 - ss * DN;   // 768 % 128 == 0: no straddle

    for (int c4 = 0; c4 < 4; c4++) {
        const bool vp = (c4 < 2);
        const float* Wsrc = vp ? (Wm + (size_t)(c4 * 128) * DCM)
                               : (Wg + (size_t)((c4 - 2) * 128) * DCM);
        // stage Wh[n][k] fp16
        #pragma unroll
        for (int t = 0; t < 8; t++) {
            int idx = tid + t * 256;          // float4 id 0..2047
            int n = idx >> 4;
            int k = (idx & 15) << 2;
            float4 w4 = *(const float4*)&Wsrc[(size_t)n * DCM + k];
            *(__half2*)&Wh[n * K1MH + k]     = __floats2half2_rn(w4.x, w4.y);
            *(__half2*)&Wh[n * K1MH + k + 2] = __floats2half2_rn(w4.z, w4.w);
        }
        __syncthreads();

        const uint32_t a_base = vp ? wh_base : mh_base;
        const uint32_t b_base = vp ? mh_base : wh_base;

        float acc[4][4][4];
        #pragma unroll
        for (int i = 0; i < 4; i++)
            #pragma unroll
            for (int j = 0; j < 4; j++)
                #pragma unroll
                for (int r = 0; r < 4; r++) acc[i][j][r] = 0.f;

        #pragma unroll
        for (int k16 = 0; k16 < 4; k16++) {
            uint32_t af[4][4], bf[4][2];
            #pragma unroll
            for (int mt = 0; mt < 4; mt++) {
                uint32_t addr = a_base + a_lane + (uint32_t)(mt * 16 * 144 + k16 * 32);
                LDSM_X4(af[mt][0], af[mt][1], af[mt][2], af[mt][3], addr);
            }
            #pragma unroll
            for (int ntp = 0; ntp < 2; ntp++) {
                uint32_t addr = b_base + b_lane + (uint32_t)(ntp * 16 * 144 + k16 * 32);
                LDSM_X4(bf[2 * ntp][0], bf[2 * ntp][1], bf[2 * ntp + 1][0], bf[2 * ntp + 1][1], addr);
            }
            #pragma unroll
            for (int mt = 0; mt < 4; mt++)
                #pragma unroll
                for (int nt = 0; nt < 4; nt++)
                    MMA_F16(acc[mt][nt], af[mt], bf[nt]);
        }

        if (vp) {
            // acc[m=channel][n=mrow]: write d_vt[h][chan][j] half2 along j
            #pragma unroll
            for (int mt = 0; mt < 4; mt++) {
                #pragma unroll
                for (int half = 0; half < 2; half++) {
                    int col = c4 * 128 + warp_m * 64 + mt * 16 + gid + half * 8;
                    int hh = col >> 5, dd = col & 31;
                    __half* dst = d_vt + ((size_t)hh * DCOL + ss * DCH + dd) * DN + jj0;
                    #pragma unroll
                    for (int nt = 0; nt < 4; nt++) {
                        int jloc = warp_n * 32 + nt * 8 + tq * 2;
                        *(__half2*)&dst[jloc] =
                            __floats2half2_rn(acc[mt][nt][half * 2],
                                              acc[mt][nt][half * 2 + 1]);
                    }
                }
            }
        } else {
            // acc[m=mrow][n=channel]: sigmoid -> d_gh
            #pragma unroll
            for (int mt = 0; mt < 4; mt++) {
                #pragma unroll
                for (int half = 0; half < 2; half++) {
                    int rowg = gr0 + warp_m * 64 + mt * 16 + gid + half * 8;
                    #pragma unroll
                    for (int nt = 0; nt < 4; nt++) {
                        int cg = (c4 - 2) * 128 + warp_n * 32 + nt * 8 + tq * 2;
                        float g0 = 1.f / (1.f + __expf(-acc[mt][nt][half * 2]));
                        float g1 = 1.f / (1.f + __expf(-acc[mt][nt][half * 2 + 1]));
                        *(__half2*)&d_gh[(size_t)rowg * DHC + cg] =
                            __floats2half2_rn(g0, g1);
                    }
                }
            }
        }
        __syncthreads();
    }
}

// ---------------------------------------------------------------------------
// K2: LN(z) + b[h][i][j] = dot(zln, Wz[h]) + mask penalty. One warp per pair.
// ---------------------------------------------------------------------------
__global__ void k2_ln_bias(const float* __restrict__ z,
                           const int* __restrict__ mask,
                           const float* __restrict__ nw,
                           const float* __restrict__ nb,
                           const float* __restrict__ Wz) {
    int gwarp = (blockIdx.x * blockDim.x + threadIdx.x) >> 5;
    int l = threadIdx.x & 31;
    if (gwarp >= DNN) return;

    const float* zr = z + (size_t)gwarp * DCZ;
    float4 xv = *(const float4*)&zr[l * 4];
    float s1 = xv.x + xv.y + xv.z + xv.w;
    float s2 = xv.x * xv.x + xv.y * xv.y + xv.z * xv.z + xv.w * xv.w;
    #pragma unroll
    for (int off = 16; off; off >>= 1) {
        s1 += __shfl_xor_sync(0xffffffffu, s1, off);
        s2 += __shfl_xor_sync(0xffffffffu, s2, off);
    }
    float mu = s1 * (1.f / 128.f);
    float inv = rsqrtf(s2 * (1.f / 128.f) - mu * mu + 1e-5f);
    float4 wv = *(const float4*)&nw[l * 4];
    float4 bv = *(const float4*)&nb[l * 4];
    float xn0 = (xv.x - mu) * inv * wv.x + bv.x;
    float xn1 = (xv.y - mu) * inv * wv.y + bv.y;
    float xn2 = (xv.z - mu) * inv * wv.z + bv.z;
    float xn3 = (xv.w - mu) * inv * wv.w + bv.w;

    float myb = 0.f;
    #pragma unroll
    for (int h = 0; h < DH; h++) {
        float4 w4 = *(const float4*)&Wz[h * DCZ + l * 4];
        float p = xn0 * w4.x + xn1 * w4.y + xn2 * w4.z + xn3 * w4.w;
        #pragma unroll
        for (int off = 16; off; off >>= 1)
            p += __shfl_xor_sync(0xffffffffu, p, off);
        if (l == h) myb = p;
    }
    if (l < DH) {
        float pen = (mask[gwarp] != 0) ? 0.f : -1e6f;
        d_b[(size_t)l * DNN + gwarp] = myb + pen;
    }
}

// ---------------------------------------------------------------------------
// K3: softmax over j (768) per (h,i) row. Reads d_b f32, writes d_bh fp16.
// ---------------------------------------------------------------------------
__global__ void k3_softmax() {
    __shared__ float sd[256];
    const float* p = d_b + (size_t)blockIdx.x * DN;
    __half* q = d_bh + (size_t)blockIdx.x * DN;
    int tid = threadIdx.x;
    float x0 = p[tid], x1 = p[tid + 256], x2 = p[tid + 512];
    float mx = fmaxf(x0, fmaxf(x1, x2));
    sd[tid] = mx; __syncthreads();
    #pragma unroll
    for (int s = 128; s; s >>= 1) {
        if (tid < s) sd[tid] = fmaxf(sd[tid], sd[tid + s]);
        __syncthreads();
    }
    float bm = sd[0]; __syncthreads();
    float e0 = __expf(x0 - bm), e1 = __expf(x1 - bm), e2 = __expf(x2 - bm);
    sd[tid] = e0 + e1 + e2; __syncthreads();
    #pragma unroll
    for (int s = 128; s; s >>= 1) {
        if (tid < s) sd[tid] += sd[tid + s];
        __syncthreads();
    }
    float invs = 1.f / sd[0];
    q[tid]       = __float2half_rn(e0 * invs);
    q[tid + 256] = __float2half_rn(e1 * invs);
    q[tid + 512] = __float2half_rn(e2 * invs);
}

// ---------------------------------------------------------------------------
// K4 v4 (fp16 mma + ldmatrix + double buffer, k32 per stage):
// Block 128x128, 8 warps (2x4), warp tile 64x32, 24 iters, 1 sync/iter.
// smem [2][128][40] halfs per operand; 80B row stride (ldmatrix conflict-free).
// ---------------------------------------------------------------------------
constexpr int K4ST = 40;                       // halfs per row
constexpr int K4BUF = 128 * K4ST;              // halfs per buffer

__global__ void __launch_bounds__(256) k4_gemm_fp16_v4() {
    __shared__ __half As[2][K4BUF];
    __shared__ __half Bs[2][K4BUF];
    const int h = blockIdx.z;
    const __half* A = d_bh + (size_t)h * DNN;
    const __half* B = d_vt + (size_t)h * DCOL * DN;
    __half* C = d_oh + (size_t)h * DN * DCOL;
    const int bm0 = blockIdx.y * 128;
    const int bn0 = blockIdx.x * 128;
    const int tid = threadIdx.x;
    const int lane = tid & 31;
    const int wid = tid >> 5;
    const int warp_m = wid >> 2;
    const int warp_n = wid & 3;
    const int gid = lane >> 2;
    const int tq  = lane & 3;

    const int r = tid >> 1;            // staging row 0..127
    const int sel = tid & 1;

    const uint32_t as_base = smem_u32(&As[0][0]);
    const uint32_t bs_base = smem_u32(&Bs[0][0]);
    const uint32_t a_lane = (uint32_t)((warp_m * 64 + (lane & 15)) * 80 + (lane >> 4) * 16);
    const uint32_t b_lane = (uint32_t)((warp_n * 32 + (lane & 7) + ((lane >> 4) & 1) * 8) * 80
                                       + ((lane >> 3) & 1) * 16);
    constexpr uint32_t BUFB = K4BUF * 2;   // bytes per buffer

    float acc[4][4][4];
    #pragma unroll
    for (int i = 0; i < 4; i++)
        #pragma unroll
        for (int j = 0; j < 4; j++)
            #pragma unroll
            for (int rr = 0; rr < 4; rr++) acc[i][j][rr] = 0.f;

    // stage tile 0 (k = 0..31)
    {
        uint4 pa0 = *(const uint4*)&A[(size_t)(bm0 + r) * DN + sel * 8];
        uint4 pa1 = *(const uint4*)&A[(size_t)(bm0 + r) * DN + 16 + sel * 8];
        uint4 pb0 = *(const uint4*)&B[(size_t)(bn0 + r) * DN + sel * 8];
        uint4 pb1 = *(const uint4*)&B[(size_t)(bn0 + r) * DN + 16 + sel * 8];
        *(uint4*)&As[0][r * K4ST + sel * 8] = pa0;
        *(uint4*)&As[0][r * K4ST + 16 + sel * 8] = pa1;
        *(uint4*)&Bs[0][r * K4ST + sel * 8] = pb0;
        *(uint4*)&Bs[0][r * K4ST + 16 + sel * 8] = pb1;
    }
    __syncthreads();

    for (int c = 0; c < 24; c++) {
        const int cur = c & 1;
        const bool more = (c + 1 < 24);
        uint4 pa0, pa1, pb0, pb1;
        if (more) {
            int kn = (c + 1) * 32;
            pa0 = *(const uint4*)&A[(size_t)(bm0 + r) * DN + kn + sel * 8];
            pa1 = *(const uint4*)&A[(size_t)(bm0 + r) * DN + kn + 16 + sel * 8];
            pb0 = *(const uint4*)&B[(size_t)(bn0 + r) * DN + kn + sel * 8];
            pb1 = *(const uint4*)&B[(size_t)(bn0 + r) * DN + kn + 16 + sel * 8];
        }

        #pragma unroll
        for (int k16 = 0; k16 < 2; k16++) {
            uint32_t af[4][4], bf[4][2];
            #pragma unroll
            for (int mt = 0; mt < 4; mt++) {
                uint32_t addr = as_base + cur * BUFB + a_lane
                              + (uint32_t)(mt * 16 * 80 + k16 * 32);
                LDSM_X4(af[mt][0], af[mt][1], af[mt][2], af[mt][3], addr);
            }
            #pragma unroll
            for (int ntp = 0; ntp < 2; ntp++) {
                uint32_t addr = bs_base + cur * BUFB + b_lane
                              + (uint32_t)(ntp * 16 * 80 + k16 * 32);
                LDSM_X4(bf[2 * ntp][0], bf[2 * ntp][1], bf[2 * ntp + 1][0], bf[2 * ntp + 1][1], addr);
            }
            #pragma unroll
            for (int mt = 0; mt < 4; mt++)
                #pragma unroll
                for (int nt = 0; nt < 4; nt++)
                    MMA_F16(acc[mt][nt], af[mt], bf[nt]);
        }

        if (more) {
            const int nxt = cur ^ 1;
            *(uint4*)&As[nxt][r * K4ST + sel * 8] = pa0;
            *(uint4*)&As[nxt][r * K4ST + 16 + sel * 8] = pa1;
            *(uint4*)&Bs[nxt][r * K4ST + sel * 8] = pb0;
            *(uint4*)&Bs[nxt][r * K4ST + 16 + sel * 8] = pb1;
        }
        __syncthreads();
    }

    #pragma unroll
    for (int mt = 0; mt < 4; mt++) {
        #pragma unroll
        for (int nt = 0; nt < 4; nt++) {
            int row = bm0 + warp_m * 64 + mt * 16 + gid;
            int col = bn0 + warp_n * 32 + nt * 8 + tq * 2;
            *(__half2*)&C[(size_t)row * DCOL + col] =
                __floats2half2_rn(acc[mt][nt][0], acc[mt][nt][1]);
            *(__half2*)&C[(size_t)(row + 8) * DCOL + col] =
                __floats2half2_rn(acc[mt][nt][2], acc[mt][nt][3]);
        }
    }
}

// ---------------------------------------------------------------------------
// K5 (fp16 mma): out[128 x 64] = (g*o_gather)[128 x 256] @ WoT[256 x 64]
// ---------------------------------------------------------------------------
constexpr int K5ST = 72;  // halfs
constexpr int K5_SMEM = (128 * K5ST + 64 * K5ST) * 2;

__global__ void k5_out_fp16(const float* __restrict__ Wo, float* __restrict__ out) {
    extern __shared__ __half sm5h[];
    __half* As = sm5h;                  // [128][64] stride 72
    __half* Bs = As + 128 * K5ST;       // [64][64]  stride 72

    const int tid = threadIdx.x;
    const int gr0 = blockIdx.x * 128;
    const int ss = gr0 / DN;
    const int i0 = gr0 - ss * DN;

    const int lane = tid & 31;
    const int wid  = tid >> 5;
    const int warp_m = wid >> 1;
    const int warp_n = wid & 1;
    const int gid = lane >> 2;
    const int tq  = lane & 3;

    float acc[2][4][4];
    #pragma unroll
    for (int i = 0; i < 2; i++)
        #pragma unroll
        for (int j = 0; j < 4; j++)
            #pragma unroll
            for (int r = 0; r < 4; r++) acc[i][j][r] = 0.f;

    for (int ck0 = 0; ck0 < DHC; ck0 += 64) {
        #pragma unroll
        for (int t = 0; t < 16; t++) {
            int idx = tid + t * 256;
            int n = idx >> 6, cl = idx & 63;
            Bs[n * K5ST + cl] = __float2half_rn(Wo[n * DHC + ck0 + cl]);
        }
        #pragma unroll
        for (int t = 0; t < 16; t++) {
            int idx = tid + t * 256;
            int r = idx >> 5;
            int cl = (idx & 31) * 2;
            int c = ck0 + cl;
            int h = c >> 5, d = c & 31;
            __half2 ov = *(const __half2*)&d_oh[((size_t)(h * DN + i0 + r) * DS + ss) * DCH + d];
            __half2 gv = *(const __half2*)&d_gh[(size_t)(gr0 + r) * DHC + c];
            float2 of = __half22float2(ov);
            float2 gf = __half22float2(gv);
            *(__half2*)&As[r * K5ST + cl] =
                __floats2half2_rn(gf.x * of.x, gf.y * of.y);
        }
        __syncthreads();

        #pragma unroll
        for (int k16 = 0; k16 < 4; k16++) {
            uint32_t af[2][4], bf[4][2];
            #pragma unroll
            for (int mt = 0; mt < 2; mt++) {
                int row = warp_m * 32 + mt * 16 + gid;
                af[mt][0] = *(const uint32_t*)&As[row * K5ST + k16 * 16 + tq * 2];
                af[mt][1] = *(const uint32_t*)&As[(row + 8) * K5ST + k16 * 16 + tq * 2];
                af[mt][2] = *(const uint32_t*)&As[row * K5ST + k16 * 16 + tq * 2 + 8];
                af[mt][3] = *(const uint32_t*)&As[(row + 8) * K5ST + k16 * 16 + tq * 2 + 8];
            }
            #pragma unroll
            for (int nt = 0; nt < 4; nt++) {
                int col = warp_n * 32 + nt * 8 + gid;
                bf[nt][0] = *(const uint32_t*)&Bs[col * K5ST + k16 * 16 + tq * 2];
                bf[nt][1] = *(const uint32_t*)&Bs[col * K5ST + k16 * 16 + tq * 2 + 8];
            }
            #pragma unroll
            for (int mt = 0; mt < 2; mt++)
                #pragma unroll
                for (int nt = 0; nt < 4; nt++)
                    MMA_F16(acc[mt][nt], af[mt], bf[nt]);
        }
        __syncthreads();
    }

    #pragma unroll
    for (int mt = 0; mt < 2; mt++) {
        #pragma unroll
        for (int nt = 0; nt < 4; nt++) {
            int row = gr0 + warp_m * 32 + mt * 16 + gid;
            int col = warp_n * 32 + nt * 8 + tq * 2;
            *(float2*)&out[(size_t)row * DCM + col] =
                make_float2(acc[mt][nt][0], acc[mt][nt][1]);
            *(float2*)&out[(size_t)(row + 8) * DCM + col] =
                make_float2(acc[mt][nt][2], acc[mt][nt][3]);
        }
    }
}

// ---------------------------------------------------------------------------
extern "C" void kernel_launch(void* const* d_in, const int* in_sizes, int n_in,
                              void* d_out, int out_size) {
    const float* m    = (const float*)d_in[0];
    const float* z    = (const float*)d_in[1];
    const int*   mask = (const int*)d_in[2];
    const float* nmw  = (const float*)d_in[3];
    const float* nmb  = (const float*)d_in[4];
    const float* nzw  = (const float*)d_in[5];
    const float* nzb  = (const float*)d_in[6];
    const float* Wm   = (const float*)d_in[7];
    const float* Wg   = (const float*)d_in[8];
    const float* Wz   = (const float*)d_in[9];
    const float* Wo   = (const float*)d_in[10];
    float* out = (float*)d_out;

    cudaFuncSetAttribute(k1_ln_vg_v2, cudaFuncAttributeMaxDynamicSharedMemorySize, K1_SMEM);
    cudaFuncSetAttribute(k5_out_fp16, cudaFuncAttributeMaxDynamicSharedMemorySize, K5_SMEM);

    k1_ln_vg_v2<<<DSN / 128, 256, K1_SMEM>>>(m, nmw, nmb, Wm, Wg);
    k2_ln_bias<<<DNN / 8, 256>>>(z, mask, nzw, nzb, Wz);
    k3_softmax<<<DH * DN, 256>>>();
    dim3 g4(DCOL / 128, DN / 128, DH);
    k4_gemm_fp16_v4<<<g4, 256>>>();
    k5_out_fp16<<<DSN / 128, 256, K5_SMEM>>>(Wo, out);
}

// round 12
// speedup vs baseline: 3.1878x; 1.1230x over previous
#include <cuda_runtime.h>
#include <cuda_fp16.h>
#include <math.h>
#include <stdint.h>

// Dims
constexpr int DS  = 256;   // S
constexpr int DN  = 768;   // N
constexpr int DCM = 64;    // CM
constexpr int DCZ = 128;   // CZ
constexpr int DH  = 8;     // heads
constexpr int DCH = 32;    // per-head channels
constexpr int DHC = 256;   // H*CH
constexpr int DSN = DS * DN;          // 196608 rows of m
constexpr int DNN = DN * DN;          // 589824 pairs
constexpr int DCOL = DS * DCH;        // 8192 GEMM cols

// Scratch (device globals; no allocations allowed)
__device__ __half d_vt[(size_t)DH * DCOL * DN];  // v^T fp16: [h][n=s*32+d][j]
__device__ __half d_bh[(size_t)DH * DNN];        // softmax probs fp16: [h][i][j]
__device__ __half d_gh[(size_t)DSN * DHC];       // gate fp16: [s*N+j][hc]
__device__ float  d_b[(size_t)DH * DNN];         // logits f32 (K2 -> K3)
__device__ __half d_oh[(size_t)DH * DN * DCOL];  // o fp16: [h][i][s*32+d]

__device__ __forceinline__ uint32_t smem_u32(const void* p) {
    uint32_t a;
    asm("{ .reg .u64 t; cvta.to.shared.u64 t, %1; cvt.u32.u64 %0, t; }"
        : "=r"(a) : "l"(p));
    return a;
}

#define MMA_F16(acc, af, bf)                                                  \
    asm volatile(                                                             \
        "mma.sync.aligned.m16n8k16.row.col.f32.f16.f16.f32 "                  \
        "{%0,%1,%2,%3}, {%4,%5,%6,%7}, {%8,%9}, {%0,%1,%2,%3};"               \
        : "+f"((acc)[0]), "+f"((acc)[1]), "+f"((acc)[2]), "+f"((acc)[3])      \
        : "r"((af)[0]), "r"((af)[1]), "r"((af)[2]), "r"((af)[3]),             \
          "r"((bf)[0]), "r"((bf)[1]))

#define LDSM_X4(r0, r1, r2, r3, addr)                                         \
    asm volatile("ldmatrix.sync.aligned.m8n8.x4.shared.b16 {%0,%1,%2,%3}, [%4];" \
        : "=r"(r0), "=r"(r1), "=r"(r2), "=r"(r3) : "r"(addr))

constexpr int STG = 136;   // staged-epilogue stride (halfs): 272 B, 16B-aligned rows

// ---------------------------------------------------------------------------
// K1 v3 (fp16 mma, single pass, coalesced staged epilogue).
// ---------------------------------------------------------------------------
constexpr int K1MH = 72;   // halfs per row (144 B stride, ldmatrix conflict-free)
constexpr int K1_SMEM = 128 * 68 * 4 + 2 * (128 * K1MH * 2) + 128 * 4;  // 72192

__global__ void __launch_bounds__(256) k1_ln_vg_v3(const float* __restrict__ m,
                                                   const float* __restrict__ nw,
                                                   const float* __restrict__ nb,
                                                   const float* __restrict__ Wm,
                                                   const float* __restrict__ Wg) {
    extern __shared__ char sm1raw[];
    float*  As  = (float*)sm1raw;                                    // [128][68]
    __half* mh  = (__half*)(sm1raw + 128 * 68 * 4);                  // [128][72]
    __half* Wh  = (__half*)(sm1raw + 128 * 68 * 4 + 128 * K1MH * 2); // [128][72]
    float*  snw = (float*)(sm1raw + 128 * 68 * 4 + 2 * 128 * K1MH * 2);
    float*  snb = snw + 64;
    __half* stage = (__half*)sm1raw;   // reuse As region after LN: [128][136] = 34816B exact

    const int tid = threadIdx.x;
    const int gr0 = blockIdx.x * 128;

    // load m tile [128][64]
    #pragma unroll
    for (int t = 0; t < 8; t++) {
        int f = tid + t * 256;
        int r = f >> 4;
        int k = (f & 15) << 2;
        float4 v4 = *(const float4*)&m[(size_t)(gr0 + r) * DCM + k];
        *(float4*)&As[r * 68 + k] = v4;
    }
    if (tid < 64) { snw[tid] = nw[tid]; snb[tid] = nb[tid]; }
    __syncthreads();

    // LN -> mh fp16
    if (tid < 128) {
        float s1 = 0.f, s2 = 0.f;
        #pragma unroll
        for (int k = 0; k < 64; k++) {
            float x = As[tid * 68 + k];
            s1 += x; s2 += x * x;
        }
        float mu  = s1 * (1.f / 64.f);
        float var = s2 * (1.f / 64.f) - mu * mu;
        float inv = rsqrtf(var + 1e-5f);
        #pragma unroll
        for (int k = 0; k < 64; k += 2) {
            float x0 = (As[tid * 68 + k]     - mu) * inv * snw[k]     + snb[k];
            float x1 = (As[tid * 68 + k + 1] - mu) * inv * snw[k + 1] + snb[k + 1];
            *(__half2*)&mh[tid * K1MH + k] = __floats2half2_rn(x0, x1);
        }
    }
    __syncthreads();

    const int lane = tid & 31;
    const int wid  = tid >> 5;
    const int warp_m = wid >> 2;   // 0..1
    const int warp_n = wid & 3;    // 0..3
    const int gid = lane >> 2;
    const int tq  = lane & 3;

    const uint32_t mh_base = smem_u32(mh);
    const uint32_t wh_base = smem_u32(Wh);
    const uint32_t a_lane = (uint32_t)((warp_m * 64 + (lane & 15)) * 144 + (lane >> 4) * 16);
    const uint32_t b_lane = (uint32_t)((warp_n * 32 + (lane & 7) + ((lane >> 4) & 1) * 8) * 144
                                       + ((lane >> 3) & 1) * 16);

    const int ss = gr0 / DN;
    const int jj0 = gr0 - ss * DN;   // 768 % 128 == 0: no straddle

    for (int c4 = 0; c4 < 4; c4++) {
        const bool vp = (c4 < 2);
        const float* Wsrc = vp ? (Wm + (size_t)(c4 * 128) * DCM)
                               : (Wg + (size_t)((c4 - 2) * 128) * DCM);
        // stage Wh[n][k] fp16
        #pragma unroll
        for (int t = 0; t < 8; t++) {
            int idx = tid + t * 256;          // float4 id 0..2047
            int n = idx >> 4;
            int k = (idx & 15) << 2;
            float4 w4 = *(const float4*)&Wsrc[(size_t)n * DCM + k];
            *(__half2*)&Wh[n * K1MH + k]     = __floats2half2_rn(w4.x, w4.y);
            *(__half2*)&Wh[n * K1MH + k + 2] = __floats2half2_rn(w4.z, w4.w);
        }
        __syncthreads();

        const uint32_t a_base = vp ? wh_base : mh_base;
        const uint32_t b_base = vp ? mh_base : wh_base;

        float acc[4][4][4];
        #pragma unroll
        for (int i = 0; i < 4; i++)
            #pragma unroll
            for (int j = 0; j < 4; j++)
                #pragma unroll
                for (int r = 0; r < 4; r++) acc[i][j][r] = 0.f;

        #pragma unroll
        for (int k16 = 0; k16 < 4; k16++) {
            uint32_t af[4][4], bf[4][2];
            #pragma unroll
            for (int mt = 0; mt < 4; mt++) {
                uint32_t addr = a_base + a_lane + (uint32_t)(mt * 16 * 144 + k16 * 32);
                LDSM_X4(af[mt][0], af[mt][1], af[mt][2], af[mt][3], addr);
            }
            #pragma unroll
            for (int ntp = 0; ntp < 2; ntp++) {
                uint32_t addr = b_base + b_lane + (uint32_t)(ntp * 16 * 144 + k16 * 32);
                LDSM_X4(bf[2 * ntp][0], bf[2 * ntp][1], bf[2 * ntp + 1][0], bf[2 * ntp + 1][1], addr);
            }
            #pragma unroll
            for (int mt = 0; mt < 4; mt++)
                #pragma unroll
                for (int nt = 0; nt < 4; nt++)
                    MMA_F16(acc[mt][nt], af[mt], bf[nt]);
        }

        // stage acc into smem (stride 136 halfs = 272B, 16B-aligned rows)
        #pragma unroll
        for (int mt = 0; mt < 4; mt++) {
            #pragma unroll
            for (int half = 0; half < 2; half++) {
                int rloc = warp_m * 64 + mt * 16 + gid + half * 8;
                #pragma unroll
                for (int nt = 0; nt < 4; nt++) {
                    int cloc = warp_n * 32 + nt * 8 + tq * 2;
                    float c0 = acc[mt][nt][half * 2];
                    float c1 = acc[mt][nt][half * 2 + 1];
                    if (!vp) {
                        c0 = 1.f / (1.f + __expf(-c0));
                        c1 = 1.f / (1.f + __expf(-c1));
                    }
                    *(__half2*)&stage[rloc * STG + cloc] = __floats2half2_rn(c0, c1);
                }
            }
        }
        __syncthreads();

        if (vp) {
            // stage rows = channel cols; write d_vt rows (256B contiguous in j)
            #pragma unroll
            for (int t = 0; t < 8; t++) {
                int idx = tid + t * 256;          // 0..2047
                int row = idx >> 4, c16 = idx & 15;
                int cglob = c4 * 128 + row;
                int hh = cglob >> 5, dd = cglob & 31;
                uint4 v = *(uint4*)&stage[row * STG + c16 * 8];
                *(uint4*)&d_vt[((size_t)hh * DCOL + ss * DCH + dd) * DN + jj0 + c16 * 8] = v;
            }
        } else {
            // stage rows = m-rows; write d_gh rows (256B contiguous in channels)
            #pragma unroll
            for (int t = 0; t < 8; t++) {
                int idx = tid + t * 256;
                int row = idx >> 4, c16 = idx & 15;
                uint4 v = *(uint4*)&stage[row * STG + c16 * 8];
                *(uint4*)&d_gh[(size_t)(gr0 + row) * DHC + (c4 - 2) * 128 + c16 * 8] = v;
            }
        }
        __syncthreads();
    }
}

// ---------------------------------------------------------------------------
// K2 v2: 4 pairs per warp (8 lanes each) for LN; head-dots via one fp16 mma
// per 16 pairs. Block = 256 threads = 32 pairs. Grid = DNN/32.
// ---------------------------------------------------------------------------
constexpr int K2ZS = 132;   // zls stride (halfs): 4B/8B accesses only
constexpr int K2WS = 136;   // Wzh stride (halfs)

__global__ void __launch_bounds__(256) k2_ln_bias_v2(const float* __restrict__ z,
                                                     const int* __restrict__ mask,
                                                     const float* __restrict__ nw,
                                                     const float* __restrict__ nb,
                                                     const float* __restrict__ Wz) {
    __shared__ __half zls[32 * K2ZS];
    __shared__ __half Wzh[8 * K2WS];
    __shared__ float nwS[128], nbS[128];

    const int tid = threadIdx.x;
    const int lane = tid & 31;
    const int wid = tid >> 5;
    const int sub = lane >> 3;       // pair within warp 0..3
    const int li  = lane & 7;        // 8 lanes per pair, 16 channels each
    const int pl  = wid * 4 + sub;   // pair local 0..31
    const size_t gp = (size_t)blockIdx.x * 32 + pl;

    // stage nw/nb/Wz
    if (tid < 128) { nwS[tid] = nw[tid]; nbS[tid] = nb[tid]; }
    {
        int n = tid >> 5, k = (tid & 31) * 4;
        float4 w4 = *(const float4*)&Wz[n * DCZ + k];
        *(__half2*)&Wzh[n * K2WS + k]     = __floats2half2_rn(w4.x, w4.y);
        *(__half2*)&Wzh[n * K2WS + k + 2] = __floats2half2_rn(w4.z, w4.w);
    }

    // load 16 channels per lane
    const float* zr = z + gp * DCZ + li * 16;
    float4 x[4];
    #pragma unroll
    for (int t = 0; t < 4; t++) x[t] = *(const float4*)&zr[t * 4];

    float s1 = 0.f, s2 = 0.f;
    #pragma unroll
    for (int t = 0; t < 4; t++) {
        s1 += x[t].x + x[t].y + x[t].z + x[t].w;
        s2 += x[t].x * x[t].x + x[t].y * x[t].y + x[t].z * x[t].z + x[t].w * x[t].w;
    }
    #pragma unroll
    for (int off = 4; off; off >>= 1) {
        s1 += __shfl_xor_sync(0xffffffffu, s1, off);
        s2 += __shfl_xor_sync(0xffffffffu, s2, off);
    }
    float mu  = s1 * (1.f / 128.f);
    float inv = rsqrtf(s2 * (1.f / 128.f) - mu * mu + 1e-5f);
    __syncthreads();   // nwS/nbS/Wzh ready

    // LN apply -> zls fp16
    {
        const float* xp = (const float*)x;
        #pragma unroll
        for (int c = 0; c < 16; c += 2) {
            int ch = li * 16 + c;
            float v0 = (xp[c]     - mu) * inv * nwS[ch]     + nbS[ch];
            float v1 = (xp[c + 1] - mu) * inv * nwS[ch + 1] + nbS[ch + 1];
            *(__half2*)&zls[pl * K2ZS + ch] = __floats2half2_rn(v0, v1);
        }
    }
    __syncthreads();

    // mma: warps 0,1 each handle 16 pairs x 8 heads, K=128
    if (wid < 2) {
        const int pb = wid * 16;
        const int gid = lane >> 2, tq = lane & 3;
        float acc[4] = {0.f, 0.f, 0.f, 0.f};
        #pragma unroll
        for (int k16 = 0; k16 < 8; k16++) {
            uint32_t af[4], bf[2];
            af[0] = *(const uint32_t*)&zls[(pb + gid) * K2ZS + k16 * 16 + tq * 2];
            af[1] = *(const uint32_t*)&zls[(pb + gid + 8) * K2ZS + k16 * 16 + tq * 2];
            af[2] = *(const uint32_t*)&zls[(pb + gid) * K2ZS + k16 * 16 + tq * 2 + 8];
            af[3] = *(const uint32_t*)&zls[(pb + gid + 8) * K2ZS + k16 * 16 + tq * 2 + 8];
            bf[0] = *(const uint32_t*)&Wzh[gid * K2WS + k16 * 16 + tq * 2];
            bf[1] = *(const uint32_t*)&Wzh[gid * K2WS + k16 * 16 + tq * 2 + 8];
            MMA_F16(acc, af, bf);
        }
        size_t gp0 = (size_t)blockIdx.x * 32 + pb + gid;
        float pen0 = (mask[gp0] != 0) ? 0.f : -1e6f;
        float pen1 = (mask[gp0 + 8] != 0) ? 0.f : -1e6f;
        d_b[(size_t)(tq * 2)     * DNN + gp0]     = acc[0] + pen0;
        d_b[(size_t)(tq * 2 + 1) * DNN + gp0]     = acc[1] + pen0;
        d_b[(size_t)(tq * 2)     * DNN + gp0 + 8] = acc[2] + pen1;
        d_b[(size_t)(tq * 2 + 1) * DNN + gp0 + 8] = acc[3] + pen1;
    }
}

// ---------------------------------------------------------------------------
// K3: softmax over j (768) per (h,i) row. Reads d_b f32, writes d_bh fp16.
// ---------------------------------------------------------------------------
__global__ void k3_softmax() {
    __shared__ float sd[256];
    const float* p = d_b + (size_t)blockIdx.x * DN;
    __half* q = d_bh + (size_t)blockIdx.x * DN;
    int tid = threadIdx.x;
    float x0 = p[tid], x1 = p[tid + 256], x2 = p[tid + 512];
    float mx = fmaxf(x0, fmaxf(x1, x2));
    sd[tid] = mx; __syncthreads();
    #pragma unroll
    for (int s = 128; s; s >>= 1) {
        if (tid < s) sd[tid] = fmaxf(sd[tid], sd[tid + s]);
        __syncthreads();
    }
    float bm = sd[0]; __syncthreads();
    float e0 = __expf(x0 - bm), e1 = __expf(x1 - bm), e2 = __expf(x2 - bm);
    sd[tid] = e0 + e1 + e2; __syncthreads();
    #pragma unroll
    for (int s = 128; s; s >>= 1) {
        if (tid < s) sd[tid] += sd[tid + s];
        __syncthreads();
    }
    float invs = 1.f / sd[0];
    q[tid]       = __float2half_rn(e0 * invs);
    q[tid + 256] = __float2half_rn(e1 * invs);
    q[tid + 512] = __float2half_rn(e2 * invs);
}

// ---------------------------------------------------------------------------
// K4 v5 (fp16 mma + ldmatrix + double buffer + staged coalesced epilogue).
// ---------------------------------------------------------------------------
constexpr int K4ST = 40;                       // halfs per row
constexpr int K4BUF = 128 * K4ST;              // halfs per buffer

__global__ void __launch_bounds__(256) k4_gemm_fp16_v5() {
    __shared__ __half sall[4 * K4BUF];         // As0|As1|Bs0|Bs1, 40KB
    const int h = blockIdx.z;
    const __half* A = d_bh + (size_t)h * DNN;
    const __half* B = d_vt + (size_t)h * DCOL * DN;
    __half* C = d_oh + (size_t)h * DN * DCOL;
    const int bm0 = blockIdx.y * 128;
    const int bn0 = blockIdx.x * 128;
    const int tid = threadIdx.x;
    const int lane = tid & 31;
    const int wid = tid >> 5;
    const int warp_m = wid >> 2;
    const int warp_n = wid & 3;
    const int gid = lane >> 2;
    const int tq  = lane & 3;

    const int r = tid >> 1;            // staging row 0..127
    const int sel = tid & 1;

    __half* As0 = sall;
    __half* Bs0 = sall + 2 * K4BUF;
    const uint32_t as_base = smem_u32(As0);
    const uint32_t bs_base = smem_u32(Bs0);
    const uint32_t a_lane = (uint32_t)((warp_m * 64 + (lane & 15)) * 80 + (lane >> 4) * 16);
    const uint32_t b_lane = (uint32_t)((warp_n * 32 + (lane & 7) + ((lane >> 4) & 1) * 8) * 80
                                       + ((lane >> 3) & 1) * 16);
    constexpr uint32_t BUFB = K4BUF * 2;   // bytes per buffer

    float acc[4][4][4];
    #pragma unroll
    for (int i = 0; i < 4; i++)
        #pragma unroll
        for (int j = 0; j < 4; j++)
            #pragma unroll
            for (int rr = 0; rr < 4; rr++) acc[i][j][rr] = 0.f;

    // stage tile 0 (k = 0..31)
    {
        uint4 pa0 = *(const uint4*)&A[(size_t)(bm0 + r) * DN + sel * 8];
        uint4 pa1 = *(const uint4*)&A[(size_t)(bm0 + r) * DN + 16 + sel * 8];
        uint4 pb0 = *(const uint4*)&B[(size_t)(bn0 + r) * DN + sel * 8];
        uint4 pb1 = *(const uint4*)&B[(size_t)(bn0 + r) * DN + 16 + sel * 8];
        *(uint4*)&As0[r * K4ST + sel * 8] = pa0;
        *(uint4*)&As0[r * K4ST + 16 + sel * 8] = pa1;
        *(uint4*)&Bs0[r * K4ST + sel * 8] = pb0;
        *(uint4*)&Bs0[r * K4ST + 16 + sel * 8] = pb1;
    }
    __syncthreads();

    for (int c = 0; c < 24; c++) {
        const int cur = c & 1;
        const bool more = (c + 1 < 24);
        uint4 pa0, pa1, pb0, pb1;
        if (more) {
            int kn = (c + 1) * 32;
            pa0 = *(const uint4*)&A[(size_t)(bm0 + r) * DN + kn + sel * 8];
            pa1 = *(const uint4*)&A[(size_t)(bm0 + r) * DN + kn + 16 + sel * 8];
            pb0 = *(const uint4*)&B[(size_t)(bn0 + r) * DN + kn + sel * 8];
            pb1 = *(const uint4*)&B[(size_t)(bn0 + r) * DN + kn + 16 + sel * 8];
        }

        #pragma unroll
        for (int k16 = 0; k16 < 2; k16++) {
            uint32_t af[4][4], bf[4][2];
            #pragma unroll
            for (int mt = 0; mt < 4; mt++) {
                uint32_t addr = as_base + cur * BUFB + a_lane
                              + (uint32_t)(mt * 16 * 80 + k16 * 32);
                LDSM_X4(af[mt][0], af[mt][1], af[mt][2], af[mt][3], addr);
            }
            #pragma unroll
            for (int ntp = 0; ntp < 2; ntp++) {
                uint32_t addr = bs_base + cur * BUFB + b_lane
                              + (uint32_t)(ntp * 16 * 80 + k16 * 32);
                LDSM_X4(bf[2 * ntp][0], bf[2 * ntp][1], bf[2 * ntp + 1][0], bf[2 * ntp + 1][1], addr);
            }
            #pragma unroll
            for (int mt = 0; mt < 4; mt++)
                #pragma unroll
                for (int nt = 0; nt < 4; nt++)
                    MMA_F16(acc[mt][nt], af[mt], bf[nt]);
        }

        if (more) {
            __half* An = sall + (cur ^ 1) * K4BUF;
            __half* Bn = sall + (2 + (cur ^ 1)) * K4BUF;
            *(uint4*)&An[r * K4ST + sel * 8] = pa0;
            *(uint4*)&An[r * K4ST + 16 + sel * 8] = pa1;
            *(uint4*)&Bn[r * K4ST + sel * 8] = pb0;
            *(uint4*)&Bn[r * K4ST + 16 + sel * 8] = pb1;
        }
        __syncthreads();
    }

    // staged coalesced epilogue (reuse sall as [128][136] halfs = 34816B < 40KB)
    __half* stage = sall;
    #pragma unroll
    for (int mt = 0; mt < 4; mt++) {
        #pragma unroll
        for (int half = 0; half < 2; half++) {
            int rloc = warp_m * 64 + mt * 16 + gid + half * 8;
            #pragma unroll
            for (int nt = 0; nt < 4; nt++) {
                int cloc = warp_n * 32 + nt * 8 + tq * 2;
                *(__half2*)&stage[rloc * STG + cloc] =
                    __floats2half2_rn(acc[mt][nt][half * 2], acc[mt][nt][half * 2 + 1]);
            }
        }
    }
    __syncthreads();
    #pragma unroll
    for (int t = 0; t < 8; t++) {
        int idx = tid + t * 256;          // 0..2047
        int row = idx >> 4, c16 = idx & 15;
        uint4 v = *(uint4*)&stage[row * STG + c16 * 8];
        *(uint4*)&C[(size_t)(bm0 + row) * DCOL + bn0 + c16 * 8] = v;
    }
}

// ---------------------------------------------------------------------------
// K5 (fp16 mma): out[128 x 64] = (g*o_gather)[128 x 256] @ WoT[256 x 64]
// ---------------------------------------------------------------------------
constexpr int K5ST = 72;  // halfs
constexpr int K5_SMEM = (128 * K5ST + 64 * K5ST) * 2;

__global__ void k5_out_fp16(const float* __restrict__ Wo, float* __restrict__ out) {
    extern __shared__ __half sm5h[];
    __half* As = sm5h;                  // [128][64] stride 72
    __half* Bs = As + 128 * K5ST;       // [64][64]  stride 72

    const int tid = threadIdx.x;
    const int gr0 = blockIdx.x * 128;
    const int ss = gr0 / DN;
    const int i0 = gr0 - ss * DN;

    const int lane = tid & 31;
    const int wid  = tid >> 5;
    const int warp_m = wid >> 1;
    const int warp_n = wid & 1;
    const int gid = lane >> 2;
    const int tq  = lane & 3;

    float acc[2][4][4];
    #pragma unroll
    for (int i = 0; i < 2; i++)
        #pragma unroll
        for (int j = 0; j < 4; j++)
            #pragma unroll
            for (int r = 0; r < 4; r++) acc[i][j][r] = 0.f;

    for (int ck0 = 0; ck0 < DHC; ck0 += 64) {
        #pragma unroll
        for (int t = 0; t < 16; t++) {
            int idx = tid + t * 256;
            int n = idx >> 6, cl = idx & 63;
            Bs[n * K5ST + cl] = __float2half_rn(Wo[n * DHC + ck0 + cl]);
        }
        #pragma unroll
        for (int t = 0; t < 16; t++) {
            int idx = tid + t * 256;
            int r = idx >> 5;
            int cl = (idx & 31) * 2;
            int c = ck0 + cl;
            int h = c >> 5, d = c & 31;
            __half2 ov = *(const __half2*)&d_oh[((size_t)(h * DN + i0 + r) * DS + ss) * DCH + d];
            __half2 gv = *(const __half2*)&d_gh[(size_t)(gr0 + r) * DHC + c];
            float2 of = __half22float2(ov);
            float2 gf = __half22float2(gv);
            *(__half2*)&As[r * K5ST + cl] =
                __floats2half2_rn(gf.x * of.x, gf.y * of.y);
        }
        __syncthreads();

        #pragma unroll
        for (int k16 = 0; k16 < 4; k16++) {
            uint32_t af[2][4], bf[4][2];
            #pragma unroll
            for (int mt = 0; mt < 2; mt++) {
                int row = warp_m * 32 + mt * 16 + gid;
                af[mt][0] = *(const uint32_t*)&As[row * K5ST + k16 * 16 + tq * 2];
                af[mt][1] = *(const uint32_t*)&As[(row + 8) * K5ST + k16 * 16 + tq * 2];
                af[mt][2] = *(const uint32_t*)&As[row * K5ST + k16 * 16 + tq * 2 + 8];
                af[mt][3] = *(const uint32_t*)&As[(row + 8) * K5ST + k16 * 16 + tq * 2 + 8];
            }
            #pragma unroll
            for (int nt = 0; nt < 4; nt++) {
                int col = warp_n * 32 + nt * 8 + gid;
                bf[nt][0] = *(const uint32_t*)&Bs[col * K5ST + k16 * 16 + tq * 2];
                bf[nt][1] = *(const uint32_t*)&Bs[col * K5ST + k16 * 16 + tq * 2 + 8];
            }
            #pragma unroll
            for (int mt = 0; mt < 2; mt++)
                #pragma unroll
                for (int nt = 0; nt < 4; nt++)
                    MMA_F16(acc[mt][nt], af[mt], bf[nt]);
        }
        __syncthreads();
    }

    #pragma unroll
    for (int mt = 0; mt < 2; mt++) {
        #pragma unroll
        for (int nt = 0; nt < 4; nt++) {
            int row = gr0 + warp_m * 32 + mt * 16 + gid;
            int col = warp_n * 32 + nt * 8 + tq * 2;
            *(float2*)&out[(size_t)row * DCM + col] =
                make_float2(acc[mt][nt][0], acc[mt][nt][1]);
            *(float2*)&out[(size_t)(row + 8) * DCM + col] =
                make_float2(acc[mt][nt][2], acc[mt][nt][3]);
        }
    }
}

// ---------------------------------------------------------------------------
extern "C" void kernel_launch(void* const* d_in, const int* in_sizes, int n_in,
                              void* d_out, int out_size) {
    const float* m    = (const float*)d_in[0];
    const float* z    = (const float*)d_in[1];
    const int*   mask = (const int*)d_in[2];
    const float* nmw  = (const float*)d_in[3];
    const float* nmb  = (const float*)d_in[4];
    const float* nzw  = (const float*)d_in[5];
    const float* nzb  = (const float*)d_in[6];
    const float* Wm   = (const float*)d_in[7];
    const float* Wg   = (const float*)d_in[8];
    const float* Wz   = (const float*)d_in[9];
    const float* Wo   = (const float*)d_in[10];
    float* out = (float*)d_out;

    cudaFuncSetAttribute(k1_ln_vg_v3, cudaFuncAttributeMaxDynamicSharedMemorySize, K1_SMEM);
    cudaFuncSetAttribute(k5_out_fp16, cudaFuncAttributeMaxDynamicSharedMemorySize, K5_SMEM);

    k1_ln_vg_v3<<<DSN / 128, 256, K1_SMEM>>>(m, nmw, nmb, Wm, Wg);
    k2_ln_bias_v2<<<DNN / 32, 256>>>(z, mask, nzw, nzb, Wz);
    k3_softmax<<<DH * DN, 256>>>();
    dim3 g4(DCOL / 128, DN / 128, DH);
    k4_gemm_fp16_v5<<<g4, 256>>>();
    k5_out_fp16<<<DSN / 128, 256, K5_SMEM>>>(Wo, out);
}